// round 11
// baseline (speedup 1.0000x reference)
#include <cuda_runtime.h>
#include <cuda_bf16.h>
#include <cuda_fp16.h>
#include <math.h>
#include <stdint.h>

#define NN 50000
#define EE 800000
#define GG 128
#define HH 128
#define CC 10
#define BCAP 64   // per-node neighbor bucket capacity (max degree ~35)

// ---------------- scratch (__device__ globals; no allocs allowed) ------------
__device__ float g_hF[2][NN * HH];           // fp32 final-layer output (pool)
__device__ __half g_x16[2][NN * HH];         // fp16 copy of x for gather
__device__ __half g_h16A[2][NN * HH];        // fp16 inter-layer activations
__device__ __half g_h16B[2][NN * HH];
__device__ float g_pool[2][GG * HH];
__device__ float g_cnt[2][GG];
__device__ int g_bcnt[2][NN];
__device__ int g_bsrc[2][NN * BCAP];
// pre-split fp16 weights: [matrix][hi/lo][128n * 68u32]
// slots: 0,1 = c1W1 ens0/1 ; 2,3 = c1W2 ens0/1 ; 4..6 = csW1 l ; 7..9 = csW2 l
__device__ uint32_t g_wsplit[10][2][8704];

// ---------------- small helpers ----------------
__device__ __forceinline__ void hsplit(float v, __half& h, __half& l) {
    h = __float2half_rn(v);
    l = __float2half_rn(v - __half2float(h));
}

// fp16 MMA, fp32 accumulate
#define MMAF16(c, a0, a1, a2, a3, b0, b1)                                    \
    asm volatile(                                                            \
        "mma.sync.aligned.m16n8k16.row.col.f32.f16.f16.f32 "                 \
        "{%0,%1,%2,%3}, {%4,%5,%6,%7}, {%8,%9}, {%0,%1,%2,%3};"              \
        : "+f"(c[0]), "+f"(c[1]), "+f"(c[2]), "+f"(c[3])                     \
        : "r"(a0), "r"(a1), "r"(a2), "r"(a3), "r"(b0), "r"(b1))

// ------- merged init: blocks 0..9 pre-split weights; rest zero counters -----
__global__ void init_prep_kernel(const float* __restrict__ c1W1,
                                 const float* __restrict__ c1W2,
                                 const float* __restrict__ csW1,
                                 const float* __restrict__ csW2) {
    if (blockIdx.x < 10) {
        int b = blockIdx.x;
        const float* W;
        if (b < 2)       W = c1W1 + (size_t)b * 16384;
        else if (b < 4)  W = c1W2 + (size_t)(b - 2) * 16384;
        else if (b < 7)  W = csW1 + (size_t)(b - 4) * 16384;
        else             W = csW2 + (size_t)(b - 7) * 16384;
        __half* whb = (__half*)g_wsplit[b][0];
        __half* wlb = (__half*)g_wsplit[b][1];
        const float4* Wv = (const float4*)W;
        for (int idx = threadIdx.x; idx < 4096; idx += 256) {
            int k = idx >> 5, nq = idx & 31;
            float4 v = Wv[k * 32 + nq];
            float vv[4] = {v.x, v.y, v.z, v.w};
#pragma unroll
            for (int i = 0; i < 4; i++) {
                int n = 4 * nq + i;
                __half h, l;
                hsplit(vv[i], h, l);
                whb[n * 136 + k] = h;   // W^T: [n][k], stride 136 half (68 u32)
                wlb[n * 136 + k] = l;
            }
        }
    } else {
        int i = (blockIdx.x - 10) * 256 + threadIdx.x;
        if (i < 2 * NN) g_bcnt[0][i] = 0;          // contiguous [2][NN]
        if (i < 2 * GG * HH) g_pool[0][i] = 0.f;
        if (i < 2 * GG) g_cnt[0][i] = 0.f;
    }
}

// ---------------- x -> fp16 conversion (8 elems/thread) ----------------
__global__ void x16_kernel(const float* __restrict__ x) {
    size_t i = ((size_t)blockIdx.x * 256 + threadIdx.x) * 8;  // < 12.8M exact
    float4 a = *(const float4*)(x + i);
    float4 b = *(const float4*)(x + i + 4);
    __half2 h0 = __floats2half2_rn(a.x, a.y);
    __half2 h1 = __floats2half2_rn(a.z, a.w);
    __half2 h2 = __floats2half2_rn(b.x, b.y);
    __half2 h3 = __floats2half2_rn(b.z, b.w);
    uint4 o;
    o.x = *(uint32_t*)&h0; o.y = *(uint32_t*)&h1;
    o.z = *(uint32_t*)&h2; o.w = *(uint32_t*)&h3;
    *(uint4*)((__half*)g_x16 + i) = o;
}

// ---------------- bucket fill ----------------
__global__ void fill_kernel(const int* __restrict__ ei) {
    int idx = blockIdx.x * 256 + threadIdx.x;
    if (idx < 2 * EE) {
        int ens = idx >= EE;
        int e = idx - ens * EE;
        const int* base = ei + (size_t)ens * 2 * EE;
        int d = base[EE + e];
        int slot = atomicAdd(&g_bcnt[ens][d], 1);
        g_bsrc[ens][(size_t)d * BCAP + slot] = base[e];
    }
}

// -------- FUSED layer kernel: gather (GIN agg) + 2x GEMM + BN epilogue ------
// smem u32: As[8704] WH[8704] WL[8704] prm[512] = 26624 u32 (106.5KB), occ 2
#define MLP_SMEM_U32 26624

__device__ __forceinline__ void copy_w(const uint32_t* __restrict__ gh,
                                       const uint32_t* __restrict__ gl,
                                       uint32_t* wh, uint32_t* wl, int tid) {
    const uint4* gh4 = (const uint4*)gh;
    const uint4* gl4 = (const uint4*)gl;
    uint4* wh4 = (uint4*)wh;
    uint4* wl4 = (uint4*)wl;
    for (int i = tid; i < 2176; i += 256) {
        wh4[i] = gh4[i];
        wl4[i] = gl4[i];
    }
}

// 32x64 warp tile GEMM on fp16 A (single) x fp16 W (hi+lo split)
__device__ __forceinline__ void do_gemm(const uint32_t* __restrict__ As,
                                        const uint32_t* __restrict__ WH,
                                        const uint32_t* __restrict__ WL,
                                        int r0, int nbase, int tg, int tp,
                                        float acc[2][8][4]) {
#pragma unroll
    for (int c = 0; c < 8; c++) {
        int ko = tp + 8 * c;
        uint32_t ah[2][4];
#pragma unroll
        for (int rs = 0; rs < 2; rs++) {
            int ar = (r0 + 16 * rs) * 68;
            int ar8 = ar + 8 * 68;
            ah[rs][0] = As[ar + ko];      ah[rs][1] = As[ar8 + ko];
            ah[rs][2] = As[ar + ko + 4];  ah[rs][3] = As[ar8 + ko + 4];
        }
#pragma unroll
        for (int j = 0; j < 8; j++) {
            int nb = (nbase + 8 * j + tg) * 68 + ko;
            uint32_t bh0 = WH[nb], bh1 = WH[nb + 4];
            uint32_t bl0 = WL[nb], bl1 = WL[nb + 4];
#pragma unroll
            for (int rs = 0; rs < 2; rs++) {
                MMAF16(acc[rs][j], ah[rs][0], ah[rs][1], ah[rs][2], ah[rs][3], bh0, bh1);
                MMAF16(acc[rs][j], ah[rs][0], ah[rs][1], ah[rs][2], ah[rs][3], bl0, bl1);
            }
        }
    }
}

__global__ __launch_bounds__(256, 2) void fused_kernel(
    const __half* __restrict__ Xbase, float* __restrict__ outbase,
    __half* __restrict__ out16base,
    int w1slot, int w1stride, int w2slot, int w2stride,
    const float* __restrict__ b1, const float* __restrict__ b2,
    const float* __restrict__ gamma, const float* __restrict__ beta,
    const float* __restrict__ mean, const float* __restrict__ var, int vs,
    const float* __restrict__ eps_p, int eps_stride) {
    extern __shared__ uint32_t sm32[];
    uint32_t* As = sm32;
    uint32_t* WH = sm32 + 8704;
    uint32_t* WL = sm32 + 17408;
    float* b1s = (float*)(sm32 + 26112);
    float* b2s = b1s + 128;
    float* scs = b2s + 128;
    float* shs = scs + 128;

    int ens = blockIdx.y;
    const __half* X = Xbase + (size_t)ens * NN * HH;
    b1 += ens * vs;  b2 += ens * vs;
    gamma += ens * vs;  beta += ens * vs;  mean += ens * vs;  var += ens * vs;
    int s1 = w1slot + ens * w1stride;
    int s2 = w2slot + ens * w2stride;

    int tid = threadIdx.x;
    int wid = tid >> 5, lane = tid & 31, tg = lane >> 2, tp = lane & 3;
    int wm = wid & 3, wcol = wid >> 2;
    int rb = blockIdx.x * 128;

    if (tid < 128) {
        b1s[tid] = b1[tid];
        b2s[tid] = b2[tid];
        float sc = gamma[tid] * rsqrtf(var[tid] + 1e-5f);
        scs[tid] = sc;
        shs[tid] = beta[tid] - mean[tid] * sc;
    }

    // ---- fused gather: warp wid owns rows wid*16 .. wid*16+15 ----
    {
        float e1 = 1.0f + eps_p[ens * eps_stride];
        const uint2* xv = (const uint2*)X;  // 32 uint2 per node row
        uint2* As2 = (uint2*)As;            // stride 34 uint2 per row
        const __half2 z2 = __floats2half2_rn(0.f, 0.f);
        for (int rr = 0; rr < 16; rr++) {
            int r = wid * 16 + rr;
            int gr = rb + r;
            uint2 o = make_uint2(0u, 0u);
            if (gr < NN) {
                const int* __restrict__ bucket =
                    &g_bsrc[ens][(size_t)gr * BCAP];
                int deg = g_bcnt[ens][gr];
                uint2 self = __ldg(&xv[(size_t)gr * 32 + lane]);
                __half2 c00 = z2, c01 = z2, c10 = z2, c11 = z2;
                int e = 0;
                for (; e + 3 < deg; e += 4) {
                    int i0 = __ldg(&bucket[e]);
                    int i1 = __ldg(&bucket[e + 1]);
                    int i2 = __ldg(&bucket[e + 2]);
                    int i3 = __ldg(&bucket[e + 3]);
                    uint2 p0 = __ldg(&xv[(size_t)(unsigned)i0 * 32 + lane]);
                    uint2 p1 = __ldg(&xv[(size_t)(unsigned)i1 * 32 + lane]);
                    uint2 p2 = __ldg(&xv[(size_t)(unsigned)i2 * 32 + lane]);
                    uint2 p3 = __ldg(&xv[(size_t)(unsigned)i3 * 32 + lane]);
                    c00 = __hadd2(c00, *(__half2*)&p0.x);
                    c01 = __hadd2(c01, *(__half2*)&p0.y);
                    c10 = __hadd2(c10, *(__half2*)&p1.x);
                    c11 = __hadd2(c11, *(__half2*)&p1.y);
                    c00 = __hadd2(c00, *(__half2*)&p2.x);
                    c01 = __hadd2(c01, *(__half2*)&p2.y);
                    c10 = __hadd2(c10, *(__half2*)&p3.x);
                    c11 = __hadd2(c11, *(__half2*)&p3.y);
                }
                for (; e < deg; e++) {
                    int sn = __ldg(&bucket[e]);
                    uint2 p = __ldg(&xv[(size_t)(unsigned)sn * 32 + lane]);
                    if (e & 1) {
                        c10 = __hadd2(c10, *(__half2*)&p.x);
                        c11 = __hadd2(c11, *(__half2*)&p.y);
                    } else {
                        c00 = __hadd2(c00, *(__half2*)&p.x);
                        c01 = __hadd2(c01, *(__half2*)&p.y);
                    }
                }
                // combine chains + (1+eps)*self in fp32
                float2 f0a = __half22float2(c00), f0b = __half22float2(c10);
                float2 f1a = __half22float2(c01), f1b = __half22float2(c11);
                float2 sl = __half22float2(*(__half2*)&self.x);
                float2 sh = __half22float2(*(__half2*)&self.y);
                float lx = f0a.x + f0b.x + e1 * sl.x;
                float ly = f0a.y + f0b.y + e1 * sl.y;
                float hx = f1a.x + f1b.x + e1 * sh.x;
                float hy = f1a.y + f1b.y + e1 * sh.y;
                __half2 o0 = __floats2half2_rn(lx, ly);
                __half2 o1 = __floats2half2_rn(hx, hy);
                o.x = *(uint32_t*)&o0;
                o.y = *(uint32_t*)&o1;
            }
            As2[r * 34 + lane] = o;
        }
    }
    copy_w(g_wsplit[s1][0], g_wsplit[s1][1], WH, WL, tid);
    __syncthreads();

    float acc[2][8][4];
#pragma unroll
    for (int rs = 0; rs < 2; rs++)
#pragma unroll
        for (int j = 0; j < 8; j++)
#pragma unroll
            for (int q = 0; q < 4; q++) acc[rs][j][q] = 0.f;

    int r0 = wm * 32 + tg;
    int nbase = wcol * 64;

    do_gemm(As, WH, WL, r0, nbase, tg, tp, acc);
    __syncthreads();

    // epilogue 1: h1 = relu(acc + b1) -> fp16 back into As (own rows/cols)
#pragma unroll
    for (int rs = 0; rs < 2; rs++) {
        int arow = (r0 + 16 * rs) * 68;
        int arow8 = arow + 8 * 68;
#pragma unroll
        for (int j = 0; j < 8; j++) {
            int col0 = nbase + 8 * j + 2 * tp;
            int cu = col0 >> 1;
            float bb0 = b1s[col0], bb1 = b1s[col0 + 1];
            float v0 = fmaxf(acc[rs][j][0] + bb0, 0.f);
            float v1 = fmaxf(acc[rs][j][1] + bb1, 0.f);
            float v2 = fmaxf(acc[rs][j][2] + bb0, 0.f);
            float v3 = fmaxf(acc[rs][j][3] + bb1, 0.f);
            __half2 p0 = __floats2half2_rn(v0, v1);
            __half2 p1 = __floats2half2_rn(v2, v3);
            As[arow + cu] = *(uint32_t*)&p0;
            As[arow8 + cu] = *(uint32_t*)&p1;
            acc[rs][j][0] = acc[rs][j][1] = acc[rs][j][2] = acc[rs][j][3] = 0.f;
        }
    }
    copy_w(g_wsplit[s2][0], g_wsplit[s2][1], WH, WL, tid);
    __syncthreads();

    do_gemm(As, WH, WL, r0, nbase, tg, tp, acc);

    // final epilogue: relu -> BN -> relu -> global (fp16 or fp32)
#pragma unroll
    for (int rs = 0; rs < 2; rs++) {
        int gr0 = rb + r0 + 16 * rs;
        int gr8 = gr0 + 8;
#pragma unroll
        for (int j = 0; j < 8; j++) {
            int col0 = nbase + 8 * j + 2 * tp;
            float bb0 = b2s[col0], bb1 = b2s[col0 + 1];
            float s0 = scs[col0], s1f = scs[col0 + 1];
            float t0 = shs[col0], t1 = shs[col0 + 1];
            float v0 = fmaxf(acc[rs][j][0] + bb0, 0.f);
            float v1 = fmaxf(acc[rs][j][1] + bb1, 0.f);
            float v2 = fmaxf(acc[rs][j][2] + bb0, 0.f);
            float v3 = fmaxf(acc[rs][j][3] + bb1, 0.f);
            float o0 = fmaxf(v0 * s0 + t0, 0.f);
            float o1 = fmaxf(v1 * s1f + t1, 0.f);
            float o2 = fmaxf(v2 * s0 + t0, 0.f);
            float o3 = fmaxf(v3 * s1f + t1, 0.f);
            if (out16base) {
                __half* o16 = out16base + (size_t)ens * NN * HH;
                if (gr0 < NN)
                    *(__half2*)(o16 + (size_t)gr0 * HH + col0) = __floats2half2_rn(o0, o1);
                if (gr8 < NN)
                    *(__half2*)(o16 + (size_t)gr8 * HH + col0) = __floats2half2_rn(o2, o3);
            } else {
                float* out = outbase + (size_t)ens * NN * HH;
                if (gr0 < NN)
                    *(float2*)(out + (size_t)gr0 * HH + col0) = make_float2(o0, o1);
                if (gr8 < NN)
                    *(float2*)(out + (size_t)gr8 * HH + col0) = make_float2(o2, o3);
            }
        }
    }
}

// ---------------- pool + head ----------------
__global__ void pool_kernel(const float* __restrict__ hbase,
                            const int* __restrict__ batch) {
    unsigned idx = blockIdx.x * 256u + threadIdx.x;
    unsigned wn = idx >> 5;
    unsigned c = (idx & 31u) << 2;
    if (wn >= 2 * NN) return;
    int ens = wn >= NN;
    unsigned n = wn - (unsigned)ens * NN;
    int g = batch[(size_t)ens * NN + n];
    const float* h = hbase + (size_t)ens * NN * HH;
    float4 v = *(const float4*)(h + (size_t)n * HH + c);
    atomicAdd((float4*)(&g_pool[ens][g * HH + c]), v);
    if (c == 0) atomicAdd(&g_cnt[ens][g], 1.0f);
}

__global__ void head_kernel(const float* __restrict__ W1all,
                            const float* __restrict__ b1all,
                            const float* __restrict__ W2all,
                            const float* __restrict__ b2all,
                            float* __restrict__ out) {
    int g = blockIdx.x;
    int ens = blockIdx.y;
    int c = threadIdx.x;  // 128 threads
    const float* W1 = W1all + (size_t)ens * 16384;
    const float* b1 = b1all + ens * 128;
    const float* W2 = W2all + (size_t)ens * 1280;
    const float* b2 = b2all + ens * 10;
    __shared__ float p[128];
    __shared__ float z[128];
    float cn = fmaxf(g_cnt[ens][g], 1.0f);
    p[c] = g_pool[ens][g * HH + c] / cn;
    __syncthreads();
    float acc = b1[c];
#pragma unroll 4
    for (int k = 0; k < 128; k++) acc += p[k] * W1[k * 128 + c];
    z[c] = fmaxf(acc, 0.f);
    __syncthreads();
    if (c < CC) {
        float y = b2[c];
#pragma unroll 4
        for (int k = 0; k < 128; k++) y += z[k] * W2[k * CC + c];
        out[((size_t)ens * GG + g) * CC + c] = y;
    }
}

// ---------------- driver ----------------
extern "C" void kernel_launch(void* const* d_in, const int* in_sizes, int n_in,
                              void* d_out, int out_size) {
    const float* x     = (const float*)d_in[0];
    const int*   ei    = (const int*)d_in[1];
    const int*   batch = (const int*)d_in[2];
    const float* c1W1  = (const float*)d_in[3];
    const float* c1b1  = (const float*)d_in[4];
    const float* c1W2  = (const float*)d_in[5];
    const float* c1b2  = (const float*)d_in[6];
    const float* c1g   = (const float*)d_in[7];
    const float* c1be  = (const float*)d_in[8];
    const float* c1m   = (const float*)d_in[9];
    const float* c1v   = (const float*)d_in[10];
    const float* c1e   = (const float*)d_in[11];
    const float* csW1  = (const float*)d_in[12];
    const float* csb1  = (const float*)d_in[13];
    const float* csW2  = (const float*)d_in[14];
    const float* csb2  = (const float*)d_in[15];
    const float* csg   = (const float*)d_in[16];
    const float* csbe  = (const float*)d_in[17];
    const float* csm   = (const float*)d_in[18];
    const float* csv   = (const float*)d_in[19];
    const float* cse   = (const float*)d_in[20];
    const float* l1W   = (const float*)d_in[21];
    const float* l1b   = (const float*)d_in[22];
    const float* l2W   = (const float*)d_in[23];
    const float* l2b   = (const float*)d_in[24];
    float* out = (float*)d_out;

    float* hF;
    __half *x16, *h16A, *h16B;
    cudaGetSymbolAddress((void**)&hF, g_hF);
    cudaGetSymbolAddress((void**)&x16, g_x16);
    cudaGetSymbolAddress((void**)&h16A, g_h16A);
    cudaGetSymbolAddress((void**)&h16B, g_h16B);

    const int SMEM_BYTES = MLP_SMEM_U32 * 4;  // 106,496 B (occ 2)
    cudaFuncSetAttribute(fused_kernel, cudaFuncAttributeMaxDynamicSharedMemorySize,
                         SMEM_BYTES);

    const int IP_GRID   = 10 + (2 * NN + 255) / 256;
    const int X16_GRID  = (2 * NN * HH) / (8 * 256);  // 12.8M exact
    const int E_GRID    = (2 * EE + 255) / 256;
    const dim3 FUSED_GRID((NN + 127) / 128, 2);
    const int POOL_GRID = (2 * NN * 32 + 255) / 256;

    init_prep_kernel<<<IP_GRID, 256>>>(c1W1, c1W2, csW1, csW2);
    x16_kernel<<<X16_GRID, 256>>>(x);
    fill_kernel<<<E_GRID, 256>>>(ei);

    // layer 0 (conv1, per-ensemble weights: slots 0+ens / 2+ens) -> fp16 out
    fused_kernel<<<FUSED_GRID, 256, SMEM_BYTES>>>(
        x16, nullptr, h16A, 0, 1, 2, 1,
        c1b1, c1b2, c1g, c1be, c1m, c1v, 128, c1e, 1);

    // layers 1..2 (shared weights: slots 4+l / 7+l) -> fp16 out
    const __half* cur = h16A;
    __half* nxt = h16B;
    for (int l = 0; l < 2; l++) {
        fused_kernel<<<FUSED_GRID, 256, SMEM_BYTES>>>(
            cur, nullptr, nxt, 4 + l, 0, 7 + l, 0,
            csb1 + l * 128, csb2 + l * 128,
            csg + l * 128, csbe + l * 128, csm + l * 128, csv + l * 128, 0,
            cse + l, 0);
        const __half* tswap = cur;
        cur = nxt;
        nxt = (__half*)tswap;
    }

    // layer 3: fp32 out for pool
    fused_kernel<<<FUSED_GRID, 256, SMEM_BYTES>>>(
        cur, hF, nullptr, 6, 0, 9, 0,
        csb1 + 2 * 128, csb2 + 2 * 128,
        csg + 2 * 128, csbe + 2 * 128, csm + 2 * 128, csv + 2 * 128, 0,
        cse + 2, 0);

    pool_kernel<<<POOL_GRID, 256>>>(hF, batch);
    head_kernel<<<dim3(GG, 2), 128>>>(l1W, l1b, l2W, l2b, out);
}

// round 12
// speedup vs baseline: 1.0734x; 1.0734x over previous
#include <cuda_runtime.h>
#include <cuda_bf16.h>
#include <cuda_fp16.h>
#include <math.h>
#include <stdint.h>

#define NN 50000
#define EE 800000
#define GG 128
#define HH 128
#define CC 10
#define BCAP 64   // per-node neighbor bucket capacity (max degree ~35)

// ---------------- scratch (__device__ globals; no allocs allowed) ------------
__device__ __half g_agg16[2][NN * HH];       // fp16 MLP input (agg output)
__device__ float g_hF[2][NN * HH];           // fp32 final-layer output (pool)
__device__ __half g_x16[2][NN * HH];         // fp16 copy of x for gather
__device__ __half g_h16A[2][NN * HH];        // fp16 inter-layer activations
__device__ __half g_h16B[2][NN * HH];
__device__ float g_pool[2][GG * HH];
__device__ float g_cnt[2][GG];
__device__ int g_bcnt[2][NN];
__device__ int g_bsrc[2][NN * BCAP];
// pre-split fp16 weights: [matrix][hi/lo][128n * 68u32]
// slots: 0,1 = c1W1 ens0/1 ; 2,3 = c1W2 ens0/1 ; 4..6 = csW1 l ; 7..9 = csW2 l
__device__ uint32_t g_wsplit[10][2][8704];

// ---------------- small helpers ----------------
__device__ __forceinline__ void hsplit(float v, __half& h, __half& l) {
    h = __float2half_rn(v);
    l = __float2half_rn(v - __half2float(h));
}

// fp16 MMA, fp32 accumulate
#define MMAF16(c, a0, a1, a2, a3, b0, b1)                                    \
    asm volatile(                                                            \
        "mma.sync.aligned.m16n8k16.row.col.f32.f16.f16.f32 "                 \
        "{%0,%1,%2,%3}, {%4,%5,%6,%7}, {%8,%9}, {%0,%1,%2,%3};"              \
        : "+f"(c[0]), "+f"(c[1]), "+f"(c[2]), "+f"(c[3])                     \
        : "r"(a0), "r"(a1), "r"(a2), "r"(a3), "r"(b0), "r"(b1))

// ------- merged init: blocks 0..9 pre-split weights; rest zero counters -----
__global__ void init_prep_kernel(const float* __restrict__ c1W1,
                                 const float* __restrict__ c1W2,
                                 const float* __restrict__ csW1,
                                 const float* __restrict__ csW2) {
    if (blockIdx.x < 10) {
        int b = blockIdx.x;
        const float* W;
        if (b < 2)       W = c1W1 + (size_t)b * 16384;
        else if (b < 4)  W = c1W2 + (size_t)(b - 2) * 16384;
        else if (b < 7)  W = csW1 + (size_t)(b - 4) * 16384;
        else             W = csW2 + (size_t)(b - 7) * 16384;
        __half* whb = (__half*)g_wsplit[b][0];
        __half* wlb = (__half*)g_wsplit[b][1];
        const float4* Wv = (const float4*)W;
        for (int idx = threadIdx.x; idx < 4096; idx += 256) {
            int k = idx >> 5, nq = idx & 31;
            float4 v = Wv[k * 32 + nq];
            float vv[4] = {v.x, v.y, v.z, v.w};
#pragma unroll
            for (int i = 0; i < 4; i++) {
                int n = 4 * nq + i;
                __half h, l;
                hsplit(vv[i], h, l);
                whb[n * 136 + k] = h;   // W^T: [n][k], stride 136 half (68 u32)
                wlb[n * 136 + k] = l;
            }
        }
    } else {
        int i = (blockIdx.x - 10) * 256 + threadIdx.x;
        if (i < 2 * NN) g_bcnt[0][i] = 0;          // contiguous [2][NN]
        if (i < 2 * GG * HH) g_pool[0][i] = 0.f;
        if (i < 2 * GG) g_cnt[0][i] = 0.f;
    }
}

// ---------------- x -> fp16 conversion (8 elems/thread) ----------------
__global__ void x16_kernel(const float* __restrict__ x) {
    size_t i = ((size_t)blockIdx.x * 256 + threadIdx.x) * 8;  // < 12.8M exact
    float4 a = *(const float4*)(x + i);
    float4 b = *(const float4*)(x + i + 4);
    __half2 h0 = __floats2half2_rn(a.x, a.y);
    __half2 h1 = __floats2half2_rn(a.z, a.w);
    __half2 h2 = __floats2half2_rn(b.x, b.y);
    __half2 h3 = __floats2half2_rn(b.z, b.w);
    uint4 o;
    o.x = *(uint32_t*)&h0; o.y = *(uint32_t*)&h1;
    o.z = *(uint32_t*)&h2; o.w = *(uint32_t*)&h3;
    *(uint4*)((__half*)g_x16 + i) = o;
}

// ---------------- bucket fill ----------------
__global__ void fill_kernel(const int* __restrict__ ei) {
    int idx = blockIdx.x * 256 + threadIdx.x;
    if (idx < 2 * EE) {
        int ens = idx >= EE;
        int e = idx - ens * EE;
        const int* base = ei + (size_t)ens * 2 * EE;
        int d = base[EE + e];
        int slot = atomicAdd(&g_bcnt[ens][d], 1);
        g_bsrc[ens][(size_t)d * BCAP + slot] = base[e];
    }
}

// warp per node: agg[n] = (1+eps)*x[n] + sum_{j in N(n)} x[j]
// int4 index loads + 8-deep gather pipeline + HADD2 chains, fp32 combine
__global__ void agg_kernel(const __half* __restrict__ xbase,
                           __half* __restrict__ aggbase,
                           const float* __restrict__ eps_p, int eps_stride) {
    unsigned idx = blockIdx.x * 256u + threadIdx.x;
    unsigned wn = idx >> 5;
    unsigned c = idx & 31u;
    if (wn >= 2 * NN) return;
    int ens = wn >= NN;
    unsigned n = wn - (unsigned)ens * NN;
    float e1 = 1.0f + eps_p[ens * eps_stride];
    const uint2* xv = (const uint2*)(xbase + (size_t)ens * NN * HH);  // 32/row
    const int* __restrict__ bucket = &g_bsrc[ens][(size_t)n * BCAP];
    const int4* __restrict__ b4 = (const int4*)bucket;  // 256B-aligned rows
    int deg = g_bcnt[ens][n];

    __half2 z2 = __floats2half2_rn(0.f, 0.f);
    __half2 a0 = z2, a1 = z2, b0 = z2, b1 = z2;
    __half2 c0 = z2, c1 = z2, d0 = z2, d1 = z2;

    uint2 self = __ldg(&xv[(size_t)n * 32 + c]);

    int e = 0;
    for (; e + 8 <= deg; e += 8) {
        int4 ia = __ldg(&b4[e >> 2]);
        int4 ib = __ldg(&b4[(e >> 2) + 1]);
        uint2 p0 = __ldg(&xv[(size_t)(unsigned)ia.x * 32 + c]);
        uint2 p1 = __ldg(&xv[(size_t)(unsigned)ia.y * 32 + c]);
        uint2 p2 = __ldg(&xv[(size_t)(unsigned)ia.z * 32 + c]);
        uint2 p3 = __ldg(&xv[(size_t)(unsigned)ia.w * 32 + c]);
        uint2 p4 = __ldg(&xv[(size_t)(unsigned)ib.x * 32 + c]);
        uint2 p5 = __ldg(&xv[(size_t)(unsigned)ib.y * 32 + c]);
        uint2 p6 = __ldg(&xv[(size_t)(unsigned)ib.z * 32 + c]);
        uint2 p7 = __ldg(&xv[(size_t)(unsigned)ib.w * 32 + c]);
        a0 = __hadd2(a0, *(__half2*)&p0.x); a1 = __hadd2(a1, *(__half2*)&p0.y);
        b0 = __hadd2(b0, *(__half2*)&p1.x); b1 = __hadd2(b1, *(__half2*)&p1.y);
        c0 = __hadd2(c0, *(__half2*)&p2.x); c1 = __hadd2(c1, *(__half2*)&p2.y);
        d0 = __hadd2(d0, *(__half2*)&p3.x); d1 = __hadd2(d1, *(__half2*)&p3.y);
        a0 = __hadd2(a0, *(__half2*)&p4.x); a1 = __hadd2(a1, *(__half2*)&p4.y);
        b0 = __hadd2(b0, *(__half2*)&p5.x); b1 = __hadd2(b1, *(__half2*)&p5.y);
        c0 = __hadd2(c0, *(__half2*)&p6.x); c1 = __hadd2(c1, *(__half2*)&p6.y);
        d0 = __hadd2(d0, *(__half2*)&p7.x); d1 = __hadd2(d1, *(__half2*)&p7.y);
    }
    if (e + 4 <= deg) {
        int4 ia = __ldg(&b4[e >> 2]);
        uint2 p0 = __ldg(&xv[(size_t)(unsigned)ia.x * 32 + c]);
        uint2 p1 = __ldg(&xv[(size_t)(unsigned)ia.y * 32 + c]);
        uint2 p2 = __ldg(&xv[(size_t)(unsigned)ia.z * 32 + c]);
        uint2 p3 = __ldg(&xv[(size_t)(unsigned)ia.w * 32 + c]);
        a0 = __hadd2(a0, *(__half2*)&p0.x); a1 = __hadd2(a1, *(__half2*)&p0.y);
        b0 = __hadd2(b0, *(__half2*)&p1.x); b1 = __hadd2(b1, *(__half2*)&p1.y);
        c0 = __hadd2(c0, *(__half2*)&p2.x); c1 = __hadd2(c1, *(__half2*)&p2.y);
        d0 = __hadd2(d0, *(__half2*)&p3.x); d1 = __hadd2(d1, *(__half2*)&p3.y);
        e += 4;
    }
    for (; e < deg; e++) {
        int sn = __ldg(&bucket[e]);
        uint2 p = __ldg(&xv[(size_t)(unsigned)sn * 32 + c]);
        if (e & 1) {
            b0 = __hadd2(b0, *(__half2*)&p.x);
            b1 = __hadd2(b1, *(__half2*)&p.y);
        } else {
            a0 = __hadd2(a0, *(__half2*)&p.x);
            a1 = __hadd2(a1, *(__half2*)&p.y);
        }
    }

    // combine 4 chains + (1+eps)*self in fp32
    float2 fa0 = __half22float2(a0), fb0 = __half22float2(b0);
    float2 fc0 = __half22float2(c0), fd0 = __half22float2(d0);
    float2 fa1 = __half22float2(a1), fb1 = __half22float2(b1);
    float2 fc1 = __half22float2(c1), fd1 = __half22float2(d1);
    float2 sl = __half22float2(*(__half2*)&self.x);
    float2 sh = __half22float2(*(__half2*)&self.y);
    float lx = (fa0.x + fb0.x) + (fc0.x + fd0.x) + e1 * sl.x;
    float ly = (fa0.y + fb0.y) + (fc0.y + fd0.y) + e1 * sl.y;
    float hx = (fa1.x + fb1.x) + (fc1.x + fd1.x) + e1 * sh.x;
    float hy = (fa1.y + fb1.y) + (fc1.y + fd1.y) + e1 * sh.y;

    __half2 o0 = __floats2half2_rn(lx, ly);
    __half2 o1 = __floats2half2_rn(hx, hy);
    uint2 o;
    o.x = *(uint32_t*)&o0; o.y = *(uint32_t*)&o1;
    ((uint2*)(aggbase + (size_t)ens * NN * HH))[(size_t)n * 32 + c] = o;
}

// ---------------- MLP: fp16 A + fp16-split W, mma.sync, occ 2 ---------------
// smem u32: As[8704] WH[8704] WL[8704] prm[512] = 26624 u32 (106.5KB)
#define MLP_SMEM_U32 26624

__device__ __forceinline__ void copy_w(const uint32_t* __restrict__ gh,
                                       const uint32_t* __restrict__ gl,
                                       uint32_t* wh, uint32_t* wl, int tid) {
    const uint4* gh4 = (const uint4*)gh;
    const uint4* gl4 = (const uint4*)gl;
    uint4* wh4 = (uint4*)wh;
    uint4* wl4 = (uint4*)wl;
    for (int i = tid; i < 2176; i += 256) {
        wh4[i] = gh4[i];
        wl4[i] = gl4[i];
    }
}

// 32x64 warp tile: rows r0+16*rs (+8), cols nbase + 8j + ...
__device__ __forceinline__ void do_gemm(const uint32_t* __restrict__ As,
                                        const uint32_t* __restrict__ WH,
                                        const uint32_t* __restrict__ WL,
                                        int r0, int nbase, int tg, int tp,
                                        float acc[2][8][4]) {
#pragma unroll
    for (int c = 0; c < 8; c++) {
        int ko = tp + 8 * c;
        uint32_t ah[2][4];
#pragma unroll
        for (int rs = 0; rs < 2; rs++) {
            int ar = (r0 + 16 * rs) * 68;
            int ar8 = ar + 8 * 68;
            ah[rs][0] = As[ar + ko];      ah[rs][1] = As[ar8 + ko];
            ah[rs][2] = As[ar + ko + 4];  ah[rs][3] = As[ar8 + ko + 4];
        }
#pragma unroll
        for (int j = 0; j < 8; j++) {
            int nb = (nbase + 8 * j + tg) * 68 + ko;
            uint32_t bh0 = WH[nb], bh1 = WH[nb + 4];
            uint32_t bl0 = WL[nb], bl1 = WL[nb + 4];
#pragma unroll
            for (int rs = 0; rs < 2; rs++) {
                MMAF16(acc[rs][j], ah[rs][0], ah[rs][1], ah[rs][2], ah[rs][3], bh0, bh1);
                MMAF16(acc[rs][j], ah[rs][0], ah[rs][1], ah[rs][2], ah[rs][3], bl0, bl1);
            }
        }
    }
}

__global__ __launch_bounds__(256, 2) void mlp_kernel(
    const __half* __restrict__ Abase, float* __restrict__ outbase,
    __half* __restrict__ out16base,
    int w1slot, int w1stride, int w2slot, int w2stride,
    const float* __restrict__ b1, const float* __restrict__ b2,
    const float* __restrict__ gamma, const float* __restrict__ beta,
    const float* __restrict__ mean, const float* __restrict__ var, int vs) {
    extern __shared__ uint32_t sm32[];
    uint32_t* As = sm32;
    uint32_t* WH = sm32 + 8704;
    uint32_t* WL = sm32 + 17408;
    float* b1s = (float*)(sm32 + 26112);
    float* b2s = b1s + 128;
    float* scs = b2s + 128;
    float* shs = scs + 128;

    int ens = blockIdx.y;
    const __half* A = Abase + (size_t)ens * NN * HH;
    b1 += ens * vs;  b2 += ens * vs;
    gamma += ens * vs;  beta += ens * vs;  mean += ens * vs;  var += ens * vs;
    int s1 = w1slot + ens * w1stride;
    int s2 = w2slot + ens * w2stride;

    int tid = threadIdx.x;
    int wid = tid >> 5, t = tid & 31, tg = t >> 2, tp = t & 3;
    int wm = wid & 3, wcol = wid >> 2;
    int rb = blockIdx.x * 128;

    if (tid < 128) {
        b1s[tid] = b1[tid];
        b2s[tid] = b2[tid];
        float sc = gamma[tid] * rsqrtf(var[tid] + 1e-5f);
        scs[tid] = sc;
        shs[tid] = beta[tid] - mean[tid] * sc;
    }

    // stage A tile (128 rows x 128 halves), pure copy
    {
        const uint2* Av = (const uint2*)A;  // 32 uint2 per row
        uint2* As2 = (uint2*)As;            // stride 34 uint2
        for (int idx = tid; idx < 4096; idx += 256) {
            int r = idx >> 5, q = idx & 31;
            int gr = rb + r;
            uint2 v = (gr < NN) ? Av[(size_t)gr * 32 + q] : make_uint2(0u, 0u);
            As2[r * 34 + q] = v;
        }
    }
    copy_w(g_wsplit[s1][0], g_wsplit[s1][1], WH, WL, tid);
    __syncthreads();

    float acc[2][8][4];
#pragma unroll
    for (int rs = 0; rs < 2; rs++)
#pragma unroll
        for (int j = 0; j < 8; j++)
#pragma unroll
            for (int q = 0; q < 4; q++) acc[rs][j][q] = 0.f;

    int r0 = wm * 32 + tg;
    int nbase = wcol * 64;

    do_gemm(As, WH, WL, r0, nbase, tg, tp, acc);
    __syncthreads();

    // epilogue 1: h1 = relu(acc + b1) -> fp16 back into As (own rows/cols)
#pragma unroll
    for (int rs = 0; rs < 2; rs++) {
        int arow = (r0 + 16 * rs) * 68;
        int arow8 = arow + 8 * 68;
#pragma unroll
        for (int j = 0; j < 8; j++) {
            int col0 = nbase + 8 * j + 2 * tp;
            int cu = col0 >> 1;
            float bb0 = b1s[col0], bb1 = b1s[col0 + 1];
            float v0 = fmaxf(acc[rs][j][0] + bb0, 0.f);
            float v1 = fmaxf(acc[rs][j][1] + bb1, 0.f);
            float v2 = fmaxf(acc[rs][j][2] + bb0, 0.f);
            float v3 = fmaxf(acc[rs][j][3] + bb1, 0.f);
            __half2 p0 = __floats2half2_rn(v0, v1);
            __half2 p1 = __floats2half2_rn(v2, v3);
            As[arow + cu] = *(uint32_t*)&p0;
            As[arow8 + cu] = *(uint32_t*)&p1;
            acc[rs][j][0] = acc[rs][j][1] = acc[rs][j][2] = acc[rs][j][3] = 0.f;
        }
    }
    copy_w(g_wsplit[s2][0], g_wsplit[s2][1], WH, WL, tid);
    __syncthreads();

    do_gemm(As, WH, WL, r0, nbase, tg, tp, acc);

    // final epilogue: relu -> BN -> relu -> global (fp16 or fp32)
#pragma unroll
    for (int rs = 0; rs < 2; rs++) {
        int gr0 = rb + r0 + 16 * rs;
        int gr8 = gr0 + 8;
#pragma unroll
        for (int j = 0; j < 8; j++) {
            int col0 = nbase + 8 * j + 2 * tp;
            float bb0 = b2s[col0], bb1 = b2s[col0 + 1];
            float s0 = scs[col0], s1f = scs[col0 + 1];
            float t0 = shs[col0], t1 = shs[col0 + 1];
            float v0 = fmaxf(acc[rs][j][0] + bb0, 0.f);
            float v1 = fmaxf(acc[rs][j][1] + bb1, 0.f);
            float v2 = fmaxf(acc[rs][j][2] + bb0, 0.f);
            float v3 = fmaxf(acc[rs][j][3] + bb1, 0.f);
            float o0 = fmaxf(v0 * s0 + t0, 0.f);
            float o1 = fmaxf(v1 * s1f + t1, 0.f);
            float o2 = fmaxf(v2 * s0 + t0, 0.f);
            float o3 = fmaxf(v3 * s1f + t1, 0.f);
            if (out16base) {
                __half* o16 = out16base + (size_t)ens * NN * HH;
                if (gr0 < NN)
                    *(__half2*)(o16 + (size_t)gr0 * HH + col0) = __floats2half2_rn(o0, o1);
                if (gr8 < NN)
                    *(__half2*)(o16 + (size_t)gr8 * HH + col0) = __floats2half2_rn(o2, o3);
            } else {
                float* out = outbase + (size_t)ens * NN * HH;
                if (gr0 < NN)
                    *(float2*)(out + (size_t)gr0 * HH + col0) = make_float2(o0, o1);
                if (gr8 < NN)
                    *(float2*)(out + (size_t)gr8 * HH + col0) = make_float2(o2, o3);
            }
        }
    }
}

// ---------------- pool + head ----------------
__global__ void pool_kernel(const float* __restrict__ hbase,
                            const int* __restrict__ batch) {
    unsigned idx = blockIdx.x * 256u + threadIdx.x;
    unsigned wn = idx >> 5;
    unsigned c = (idx & 31u) << 2;
    if (wn >= 2 * NN) return;
    int ens = wn >= NN;
    unsigned n = wn - (unsigned)ens * NN;
    int g = batch[(size_t)ens * NN + n];
    const float* h = hbase + (size_t)ens * NN * HH;
    float4 v = *(const float4*)(h + (size_t)n * HH + c);
    atomicAdd((float4*)(&g_pool[ens][g * HH + c]), v);
    if (c == 0) atomicAdd(&g_cnt[ens][g], 1.0f);
}

__global__ void head_kernel(const float* __restrict__ W1all,
                            const float* __restrict__ b1all,
                            const float* __restrict__ W2all,
                            const float* __restrict__ b2all,
                            float* __restrict__ out) {
    int g = blockIdx.x;
    int ens = blockIdx.y;
    int c = threadIdx.x;  // 128 threads
    const float* W1 = W1all + (size_t)ens * 16384;
    const float* b1 = b1all + ens * 128;
    const float* W2 = W2all + (size_t)ens * 1280;
    const float* b2 = b2all + ens * 10;
    __shared__ float p[128];
    __shared__ float z[128];
    float cn = fmaxf(g_cnt[ens][g], 1.0f);
    p[c] = g_pool[ens][g * HH + c] / cn;
    __syncthreads();
    float acc = b1[c];
#pragma unroll 4
    for (int k = 0; k < 128; k++) acc += p[k] * W1[k * 128 + c];
    z[c] = fmaxf(acc, 0.f);
    __syncthreads();
    if (c < CC) {
        float y = b2[c];
#pragma unroll 4
        for (int k = 0; k < 128; k++) y += z[k] * W2[k * CC + c];
        out[((size_t)ens * GG + g) * CC + c] = y;
    }
}

// ---------------- driver ----------------
extern "C" void kernel_launch(void* const* d_in, const int* in_sizes, int n_in,
                              void* d_out, int out_size) {
    const float* x     = (const float*)d_in[0];
    const int*   ei    = (const int*)d_in[1];
    const int*   batch = (const int*)d_in[2];
    const float* c1W1  = (const float*)d_in[3];
    const float* c1b1  = (const float*)d_in[4];
    const float* c1W2  = (const float*)d_in[5];
    const float* c1b2  = (const float*)d_in[6];
    const float* c1g   = (const float*)d_in[7];
    const float* c1be  = (const float*)d_in[8];
    const float* c1m   = (const float*)d_in[9];
    const float* c1v   = (const float*)d_in[10];
    const float* c1e   = (const float*)d_in[11];
    const float* csW1  = (const float*)d_in[12];
    const float* csb1  = (const float*)d_in[13];
    const float* csW2  = (const float*)d_in[14];
    const float* csb2  = (const float*)d_in[15];
    const float* csg   = (const float*)d_in[16];
    const float* csbe  = (const float*)d_in[17];
    const float* csm   = (const float*)d_in[18];
    const float* csv   = (const float*)d_in[19];
    const float* cse   = (const float*)d_in[20];
    const float* l1W   = (const float*)d_in[21];
    const float* l1b   = (const float*)d_in[22];
    const float* l2W   = (const float*)d_in[23];
    const float* l2b   = (const float*)d_in[24];
    float* out = (float*)d_out;

    float* hF;
    __half *agg16, *x16, *h16A, *h16B;
    cudaGetSymbolAddress((void**)&agg16, g_agg16);
    cudaGetSymbolAddress((void**)&hF, g_hF);
    cudaGetSymbolAddress((void**)&x16, g_x16);
    cudaGetSymbolAddress((void**)&h16A, g_h16A);
    cudaGetSymbolAddress((void**)&h16B, g_h16B);

    const int SMEM_BYTES = MLP_SMEM_U32 * 4;  // 106,496 B (occ 2)
    cudaFuncSetAttribute(mlp_kernel, cudaFuncAttributeMaxDynamicSharedMemorySize,
                         SMEM_BYTES);

    const int IP_GRID   = 10 + (2 * NN + 255) / 256;
    const int X16_GRID  = (2 * NN * HH) / (8 * 256);  // 12.8M exact
    const int E_GRID    = (2 * EE + 255) / 256;
    const int AGG_GRID  = (2 * NN * 32 + 255) / 256;
    const dim3 MLP_GRID((NN + 127) / 128, 2);
    const int POOL_GRID = (2 * NN * 32 + 255) / 256;

    init_prep_kernel<<<IP_GRID, 256>>>(c1W1, c1W2, csW1, csW2);
    x16_kernel<<<X16_GRID, 256>>>(x);
    fill_kernel<<<E_GRID, 256>>>(ei);

    // layer 0 (conv1, per-ensemble weights: slots 0+ens / 2+ens) -> fp16 out
    agg_kernel<<<AGG_GRID, 256>>>(x16, agg16, c1e, 1);
    mlp_kernel<<<MLP_GRID, 256, SMEM_BYTES>>>(
        agg16, nullptr, h16A, 0, 1, 2, 1, c1b1, c1b2, c1g, c1be, c1m, c1v, 128);

    // layers 1..2 (shared weights: slots 4+l / 7+l) -> fp16 out
    const __half* cur = h16A;
    __half* nxt = h16B;
    for (int l = 0; l < 2; l++) {
        agg_kernel<<<AGG_GRID, 256>>>(cur, agg16, cse + l, 0);
        mlp_kernel<<<MLP_GRID, 256, SMEM_BYTES>>>(
            agg16, nullptr, nxt, 4 + l, 0, 7 + l, 0,
            csb1 + l * 128, csb2 + l * 128,
            csg + l * 128, csbe + l * 128, csm + l * 128, csv + l * 128, 0);
        const __half* tswap = cur;
        cur = nxt;
        nxt = (__half*)tswap;
    }

    // layer 3: fp32 out for pool
    agg_kernel<<<AGG_GRID, 256>>>(cur, agg16, cse + 2, 0);
    mlp_kernel<<<MLP_GRID, 256, SMEM_BYTES>>>(
        agg16, hF, nullptr, 6, 0, 9, 0,
        csb1 + 2 * 128, csb2 + 2 * 128,
        csg + 2 * 128, csbe + 2 * 128, csm + 2 * 128, csv + 2 * 128, 0);

    pool_kernel<<<POOL_GRID, 256>>>(hF, batch);
    head_kernel<<<dim3(GG, 2), 128>>>(l1W, l1b, l2W, l2b, out);
}

// round 13
// speedup vs baseline: 1.1213x; 1.0446x over previous
#include <cuda_runtime.h>
#include <cuda_bf16.h>
#include <cuda_fp16.h>
#include <math.h>
#include <stdint.h>

#define NN 50000
#define EE 800000
#define GG 128
#define HH 128
#define CC 10
#define BCAP 64   // per-node neighbor bucket capacity (max degree ~35)

// ---------------- scratch (__device__ globals; no allocs allowed) ------------
__device__ __half g_agg16[2][NN * HH];       // fp16 MLP input (agg output)
__device__ float g_hF[2][NN * HH];           // fp32 final-layer output (pool)
__device__ __half g_x16[2][NN * HH];         // fp16 copy of x for gather
__device__ __half g_h16A[2][NN * HH];        // fp16 inter-layer activations
__device__ __half g_h16B[2][NN * HH];
__device__ float g_pool[2][GG * HH];
__device__ float g_cnt[2][GG];
__device__ int g_bcnt[2][NN];
__device__ int g_bsrc[2][NN * BCAP];
// pre-split fp16 weights: [matrix][hi/lo][128n * 68u32]
// slots: 0,1 = c1W1 ens0/1 ; 2,3 = c1W2 ens0/1 ; 4..6 = csW1 l ; 7..9 = csW2 l
__device__ uint32_t g_wsplit[10][2][8704];

// ---------------- small helpers ----------------
__device__ __forceinline__ void hsplit(float v, __half& h, __half& l) {
    h = __float2half_rn(v);
    l = __float2half_rn(v - __half2float(h));
}

// fp16 MMA, fp32 accumulate
#define MMAF16(c, a0, a1, a2, a3, b0, b1)                                    \
    asm volatile(                                                            \
        "mma.sync.aligned.m16n8k16.row.col.f32.f16.f16.f32 "                 \
        "{%0,%1,%2,%3}, {%4,%5,%6,%7}, {%8,%9}, {%0,%1,%2,%3};"              \
        : "+f"(c[0]), "+f"(c[1]), "+f"(c[2]), "+f"(c[3])                     \
        : "r"(a0), "r"(a1), "r"(a2), "r"(a3), "r"(b0), "r"(b1))

// ------- merged init: blocks 0..9 pre-split weights; rest zero counters -----
__global__ void init_prep_kernel(const float* __restrict__ c1W1,
                                 const float* __restrict__ c1W2,
                                 const float* __restrict__ csW1,
                                 const float* __restrict__ csW2) {
    if (blockIdx.x < 10) {
        int b = blockIdx.x;
        const float* W;
        if (b < 2)       W = c1W1 + (size_t)b * 16384;
        else if (b < 4)  W = c1W2 + (size_t)(b - 2) * 16384;
        else if (b < 7)  W = csW1 + (size_t)(b - 4) * 16384;
        else             W = csW2 + (size_t)(b - 7) * 16384;
        __half* whb = (__half*)g_wsplit[b][0];
        __half* wlb = (__half*)g_wsplit[b][1];
        const float4* Wv = (const float4*)W;
        for (int idx = threadIdx.x; idx < 4096; idx += 256) {
            int k = idx >> 5, nq = idx & 31;
            float4 v = Wv[k * 32 + nq];
            float vv[4] = {v.x, v.y, v.z, v.w};
#pragma unroll
            for (int i = 0; i < 4; i++) {
                int n = 4 * nq + i;
                __half h, l;
                hsplit(vv[i], h, l);
                whb[n * 136 + k] = h;   // W^T: [n][k], stride 136 half (68 u32)
                wlb[n * 136 + k] = l;
            }
        }
    } else {
        int i = (blockIdx.x - 10) * 256 + threadIdx.x;
        if (i < 2 * NN) g_bcnt[0][i] = 0;          // contiguous [2][NN]
        if (i < 2 * GG * HH) g_pool[0][i] = 0.f;
        if (i < 2 * GG) g_cnt[0][i] = 0.f;
    }
}

// ---------------- x -> fp16 conversion (8 elems/thread) ----------------
__global__ void x16_kernel(const float* __restrict__ x) {
    size_t i = ((size_t)blockIdx.x * 256 + threadIdx.x) * 8;  // < 12.8M exact
    float4 a = *(const float4*)(x + i);
    float4 b = *(const float4*)(x + i + 4);
    __half2 h0 = __floats2half2_rn(a.x, a.y);
    __half2 h1 = __floats2half2_rn(a.z, a.w);
    __half2 h2 = __floats2half2_rn(b.x, b.y);
    __half2 h3 = __floats2half2_rn(b.z, b.w);
    uint4 o;
    o.x = *(uint32_t*)&h0; o.y = *(uint32_t*)&h1;
    o.z = *(uint32_t*)&h2; o.w = *(uint32_t*)&h3;
    *(uint4*)((__half*)g_x16 + i) = o;
}

// ---------------- bucket fill ----------------
__global__ void fill_kernel(const int* __restrict__ ei) {
    int idx = blockIdx.x * 256 + threadIdx.x;
    if (idx < 2 * EE) {
        int ens = idx >= EE;
        int e = idx - ens * EE;
        const int* base = ei + (size_t)ens * 2 * EE;
        int d = base[EE + e];
        int slot = atomicAdd(&g_bcnt[ens][d], 1);
        g_bsrc[ens][(size_t)d * BCAP + slot] = base[e];
    }
}

// warp per node: agg[n] = (1+eps)*x[n] + sum_{j in N(n)} x[j]
// int4 index loads + gather pipeline + HADD2 chains, fp32 combine
// __launch_bounds__(256, 6): cap at 40 regs -> 6 CTAs/SM (75% occ)
__global__ __launch_bounds__(256, 6) void agg_kernel(
    const __half* __restrict__ xbase,
    __half* __restrict__ aggbase,
    const float* __restrict__ eps_p, int eps_stride) {
    unsigned idx = blockIdx.x * 256u + threadIdx.x;
    unsigned wn = idx >> 5;
    unsigned c = idx & 31u;
    if (wn >= 2 * NN) return;
    int ens = wn >= NN;
    unsigned n = wn - (unsigned)ens * NN;
    float e1 = 1.0f + eps_p[ens * eps_stride];
    const uint2* xv = (const uint2*)(xbase + (size_t)ens * NN * HH);  // 32/row
    const int* __restrict__ bucket = &g_bsrc[ens][(size_t)n * BCAP];
    const int4* __restrict__ b4 = (const int4*)bucket;  // 256B-aligned rows
    int deg = g_bcnt[ens][n];

    __half2 z2 = __floats2half2_rn(0.f, 0.f);
    __half2 a0 = z2, a1 = z2, b0 = z2, b1 = z2;
    __half2 c0 = z2, c1 = z2, d0 = z2, d1 = z2;

    uint2 self = __ldg(&xv[(size_t)n * 32 + c]);

    int e = 0;
    for (; e + 8 <= deg; e += 8) {
        int4 ia = __ldg(&b4[e >> 2]);
        int4 ib = __ldg(&b4[(e >> 2) + 1]);
        uint2 p0 = __ldg(&xv[(size_t)(unsigned)ia.x * 32 + c]);
        uint2 p1 = __ldg(&xv[(size_t)(unsigned)ia.y * 32 + c]);
        uint2 p2 = __ldg(&xv[(size_t)(unsigned)ia.z * 32 + c]);
        uint2 p3 = __ldg(&xv[(size_t)(unsigned)ia.w * 32 + c]);
        uint2 p4 = __ldg(&xv[(size_t)(unsigned)ib.x * 32 + c]);
        uint2 p5 = __ldg(&xv[(size_t)(unsigned)ib.y * 32 + c]);
        uint2 p6 = __ldg(&xv[(size_t)(unsigned)ib.z * 32 + c]);
        uint2 p7 = __ldg(&xv[(size_t)(unsigned)ib.w * 32 + c]);
        a0 = __hadd2(a0, *(__half2*)&p0.x); a1 = __hadd2(a1, *(__half2*)&p0.y);
        b0 = __hadd2(b0, *(__half2*)&p1.x); b1 = __hadd2(b1, *(__half2*)&p1.y);
        c0 = __hadd2(c0, *(__half2*)&p2.x); c1 = __hadd2(c1, *(__half2*)&p2.y);
        d0 = __hadd2(d0, *(__half2*)&p3.x); d1 = __hadd2(d1, *(__half2*)&p3.y);
        a0 = __hadd2(a0, *(__half2*)&p4.x); a1 = __hadd2(a1, *(__half2*)&p4.y);
        b0 = __hadd2(b0, *(__half2*)&p5.x); b1 = __hadd2(b1, *(__half2*)&p5.y);
        c0 = __hadd2(c0, *(__half2*)&p6.x); c1 = __hadd2(c1, *(__half2*)&p6.y);
        d0 = __hadd2(d0, *(__half2*)&p7.x); d1 = __hadd2(d1, *(__half2*)&p7.y);
    }
    if (e + 4 <= deg) {
        int4 ia = __ldg(&b4[e >> 2]);
        uint2 p0 = __ldg(&xv[(size_t)(unsigned)ia.x * 32 + c]);
        uint2 p1 = __ldg(&xv[(size_t)(unsigned)ia.y * 32 + c]);
        uint2 p2 = __ldg(&xv[(size_t)(unsigned)ia.z * 32 + c]);
        uint2 p3 = __ldg(&xv[(size_t)(unsigned)ia.w * 32 + c]);
        a0 = __hadd2(a0, *(__half2*)&p0.x); a1 = __hadd2(a1, *(__half2*)&p0.y);
        b0 = __hadd2(b0, *(__half2*)&p1.x); b1 = __hadd2(b1, *(__half2*)&p1.y);
        c0 = __hadd2(c0, *(__half2*)&p2.x); c1 = __hadd2(c1, *(__half2*)&p2.y);
        d0 = __hadd2(d0, *(__half2*)&p3.x); d1 = __hadd2(d1, *(__half2*)&p3.y);
        e += 4;
    }
    for (; e < deg; e++) {
        int sn = __ldg(&bucket[e]);
        uint2 p = __ldg(&xv[(size_t)(unsigned)sn * 32 + c]);
        if (e & 1) {
            b0 = __hadd2(b0, *(__half2*)&p.x);
            b1 = __hadd2(b1, *(__half2*)&p.y);
        } else {
            a0 = __hadd2(a0, *(__half2*)&p.x);
            a1 = __hadd2(a1, *(__half2*)&p.y);
        }
    }

    // combine 4 chains + (1+eps)*self in fp32
    float2 fa0 = __half22float2(a0), fb0 = __half22float2(b0);
    float2 fc0 = __half22float2(c0), fd0 = __half22float2(d0);
    float2 fa1 = __half22float2(a1), fb1 = __half22float2(b1);
    float2 fc1 = __half22float2(c1), fd1 = __half22float2(d1);
    float2 sl = __half22float2(*(__half2*)&self.x);
    float2 sh = __half22float2(*(__half2*)&self.y);
    float lx = (fa0.x + fb0.x) + (fc0.x + fd0.x) + e1 * sl.x;
    float ly = (fa0.y + fb0.y) + (fc0.y + fd0.y) + e1 * sl.y;
    float hx = (fa1.x + fb1.x) + (fc1.x + fd1.x) + e1 * sh.x;
    float hy = (fa1.y + fb1.y) + (fc1.y + fd1.y) + e1 * sh.y;

    __half2 o0 = __floats2half2_rn(lx, ly);
    __half2 o1 = __floats2half2_rn(hx, hy);
    uint2 o;
    o.x = *(uint32_t*)&o0; o.y = *(uint32_t*)&o1;
    ((uint2*)(aggbase + (size_t)ens * NN * HH))[(size_t)n * 32 + c] = o;
}

// ---------------- MLP: fp16 A + fp16-split W, mma.sync, occ 2 ---------------
// smem u32: As[8704] WH[8704] WL[8704] prm[512] = 26624 u32 (106.5KB)
#define MLP_SMEM_U32 26624

__device__ __forceinline__ void copy_w(const uint32_t* __restrict__ gh,
                                       const uint32_t* __restrict__ gl,
                                       uint32_t* wh, uint32_t* wl, int tid) {
    const uint4* gh4 = (const uint4*)gh;
    const uint4* gl4 = (const uint4*)gl;
    uint4* wh4 = (uint4*)wh;
    uint4* wl4 = (uint4*)wl;
    for (int i = tid; i < 2176; i += 256) {
        wh4[i] = gh4[i];
        wl4[i] = gl4[i];
    }
}

// 32x64 warp tile: rows r0+16*rs (+8), cols nbase + 8j + ...
__device__ __forceinline__ void do_gemm(const uint32_t* __restrict__ As,
                                        const uint32_t* __restrict__ WH,
                                        const uint32_t* __restrict__ WL,
                                        int r0, int nbase, int tg, int tp,
                                        float acc[2][8][4]) {
#pragma unroll
    for (int c = 0; c < 8; c++) {
        int ko = tp + 8 * c;
        uint32_t ah[2][4];
#pragma unroll
        for (int rs = 0; rs < 2; rs++) {
            int ar = (r0 + 16 * rs) * 68;
            int ar8 = ar + 8 * 68;
            ah[rs][0] = As[ar + ko];      ah[rs][1] = As[ar8 + ko];
            ah[rs][2] = As[ar + ko + 4];  ah[rs][3] = As[ar8 + ko + 4];
        }
#pragma unroll
        for (int j = 0; j < 8; j++) {
            int nb = (nbase + 8 * j + tg) * 68 + ko;
            uint32_t bh0 = WH[nb], bh1 = WH[nb + 4];
            uint32_t bl0 = WL[nb], bl1 = WL[nb + 4];
#pragma unroll
            for (int rs = 0; rs < 2; rs++) {
                MMAF16(acc[rs][j], ah[rs][0], ah[rs][1], ah[rs][2], ah[rs][3], bh0, bh1);
                MMAF16(acc[rs][j], ah[rs][0], ah[rs][1], ah[rs][2], ah[rs][3], bl0, bl1);
            }
        }
    }
}

__global__ __launch_bounds__(256, 2) void mlp_kernel(
    const __half* __restrict__ Abase, float* __restrict__ outbase,
    __half* __restrict__ out16base,
    int w1slot, int w1stride, int w2slot, int w2stride,
    const float* __restrict__ b1, const float* __restrict__ b2,
    const float* __restrict__ gamma, const float* __restrict__ beta,
    const float* __restrict__ mean, const float* __restrict__ var, int vs) {
    extern __shared__ uint32_t sm32[];
    uint32_t* As = sm32;
    uint32_t* WH = sm32 + 8704;
    uint32_t* WL = sm32 + 17408;
    float* b1s = (float*)(sm32 + 26112);
    float* b2s = b1s + 128;
    float* scs = b2s + 128;
    float* shs = scs + 128;

    int ens = blockIdx.y;
    const __half* A = Abase + (size_t)ens * NN * HH;
    b1 += ens * vs;  b2 += ens * vs;
    gamma += ens * vs;  beta += ens * vs;  mean += ens * vs;  var += ens * vs;
    int s1 = w1slot + ens * w1stride;
    int s2 = w2slot + ens * w2stride;

    int tid = threadIdx.x;
    int wid = tid >> 5, t = tid & 31, tg = t >> 2, tp = t & 3;
    int wm = wid & 3, wcol = wid >> 2;
    int rb = blockIdx.x * 128;

    if (tid < 128) {
        b1s[tid] = b1[tid];
        b2s[tid] = b2[tid];
        float sc = gamma[tid] * rsqrtf(var[tid] + 1e-5f);
        scs[tid] = sc;
        shs[tid] = beta[tid] - mean[tid] * sc;
    }

    // stage A tile (128 rows x 128 halves), pure copy
    {
        const uint2* Av = (const uint2*)A;  // 32 uint2 per row
        uint2* As2 = (uint2*)As;            // stride 34 uint2
        for (int idx = tid; idx < 4096; idx += 256) {
            int r = idx >> 5, q = idx & 31;
            int gr = rb + r;
            uint2 v = (gr < NN) ? Av[(size_t)gr * 32 + q] : make_uint2(0u, 0u);
            As2[r * 34 + q] = v;
        }
    }
    copy_w(g_wsplit[s1][0], g_wsplit[s1][1], WH, WL, tid);
    __syncthreads();

    float acc[2][8][4];
#pragma unroll
    for (int rs = 0; rs < 2; rs++)
#pragma unroll
        for (int j = 0; j < 8; j++)
#pragma unroll
            for (int q = 0; q < 4; q++) acc[rs][j][q] = 0.f;

    int r0 = wm * 32 + tg;
    int nbase = wcol * 64;

    do_gemm(As, WH, WL, r0, nbase, tg, tp, acc);
    __syncthreads();

    // epilogue 1: h1 = relu(acc + b1) -> fp16 back into As (own rows/cols)
#pragma unroll
    for (int rs = 0; rs < 2; rs++) {
        int arow = (r0 + 16 * rs) * 68;
        int arow8 = arow + 8 * 68;
#pragma unroll
        for (int j = 0; j < 8; j++) {
            int col0 = nbase + 8 * j + 2 * tp;
            int cu = col0 >> 1;
            float bb0 = b1s[col0], bb1 = b1s[col0 + 1];
            float v0 = fmaxf(acc[rs][j][0] + bb0, 0.f);
            float v1 = fmaxf(acc[rs][j][1] + bb1, 0.f);
            float v2 = fmaxf(acc[rs][j][2] + bb0, 0.f);
            float v3 = fmaxf(acc[rs][j][3] + bb1, 0.f);
            __half2 p0 = __floats2half2_rn(v0, v1);
            __half2 p1 = __floats2half2_rn(v2, v3);
            As[arow + cu] = *(uint32_t*)&p0;
            As[arow8 + cu] = *(uint32_t*)&p1;
            acc[rs][j][0] = acc[rs][j][1] = acc[rs][j][2] = acc[rs][j][3] = 0.f;
        }
    }
    copy_w(g_wsplit[s2][0], g_wsplit[s2][1], WH, WL, tid);
    __syncthreads();

    do_gemm(As, WH, WL, r0, nbase, tg, tp, acc);

    // final epilogue: relu -> BN -> relu -> global (fp16 or fp32)
#pragma unroll
    for (int rs = 0; rs < 2; rs++) {
        int gr0 = rb + r0 + 16 * rs;
        int gr8 = gr0 + 8;
#pragma unroll
        for (int j = 0; j < 8; j++) {
            int col0 = nbase + 8 * j + 2 * tp;
            float bb0 = b2s[col0], bb1 = b2s[col0 + 1];
            float s0 = scs[col0], s1f = scs[col0 + 1];
            float t0 = shs[col0], t1 = shs[col0 + 1];
            float v0 = fmaxf(acc[rs][j][0] + bb0, 0.f);
            float v1 = fmaxf(acc[rs][j][1] + bb1, 0.f);
            float v2 = fmaxf(acc[rs][j][2] + bb0, 0.f);
            float v3 = fmaxf(acc[rs][j][3] + bb1, 0.f);
            float o0 = fmaxf(v0 * s0 + t0, 0.f);
            float o1 = fmaxf(v1 * s1f + t1, 0.f);
            float o2 = fmaxf(v2 * s0 + t0, 0.f);
            float o3 = fmaxf(v3 * s1f + t1, 0.f);
            if (out16base) {
                __half* o16 = out16base + (size_t)ens * NN * HH;
                if (gr0 < NN)
                    *(__half2*)(o16 + (size_t)gr0 * HH + col0) = __floats2half2_rn(o0, o1);
                if (gr8 < NN)
                    *(__half2*)(o16 + (size_t)gr8 * HH + col0) = __floats2half2_rn(o2, o3);
            } else {
                float* out = outbase + (size_t)ens * NN * HH;
                if (gr0 < NN)
                    *(float2*)(out + (size_t)gr0 * HH + col0) = make_float2(o0, o1);
                if (gr8 < NN)
                    *(float2*)(out + (size_t)gr8 * HH + col0) = make_float2(o2, o3);
            }
        }
    }
}

// ---------------- pool + head ----------------
__global__ void pool_kernel(const float* __restrict__ hbase,
                            const int* __restrict__ batch) {
    unsigned idx = blockIdx.x * 256u + threadIdx.x;
    unsigned wn = idx >> 5;
    unsigned c = (idx & 31u) << 2;
    if (wn >= 2 * NN) return;
    int ens = wn >= NN;
    unsigned n = wn - (unsigned)ens * NN;
    int g = batch[(size_t)ens * NN + n];
    const float* h = hbase + (size_t)ens * NN * HH;
    float4 v = *(const float4*)(h + (size_t)n * HH + c);
    atomicAdd((float4*)(&g_pool[ens][g * HH + c]), v);
    if (c == 0) atomicAdd(&g_cnt[ens][g], 1.0f);
}

__global__ void head_kernel(const float* __restrict__ W1all,
                            const float* __restrict__ b1all,
                            const float* __restrict__ W2all,
                            const float* __restrict__ b2all,
                            float* __restrict__ out) {
    int g = blockIdx.x;
    int ens = blockIdx.y;
    int c = threadIdx.x;  // 128 threads
    const float* W1 = W1all + (size_t)ens * 16384;
    const float* b1 = b1all + ens * 128;
    const float* W2 = W2all + (size_t)ens * 1280;
    const float* b2 = b2all + ens * 10;
    __shared__ float p[128];
    __shared__ float z[128];
    float cn = fmaxf(g_cnt[ens][g], 1.0f);
    p[c] = g_pool[ens][g * HH + c] / cn;
    __syncthreads();
    float acc = b1[c];
#pragma unroll 4
    for (int k = 0; k < 128; k++) acc += p[k] * W1[k * 128 + c];
    z[c] = fmaxf(acc, 0.f);
    __syncthreads();
    if (c < CC) {
        float y = b2[c];
#pragma unroll 4
        for (int k = 0; k < 128; k++) y += z[k] * W2[k * CC + c];
        out[((size_t)ens * GG + g) * CC + c] = y;
    }
}

// ---------------- driver ----------------
extern "C" void kernel_launch(void* const* d_in, const int* in_sizes, int n_in,
                              void* d_out, int out_size) {
    const float* x     = (const float*)d_in[0];
    const int*   ei    = (const int*)d_in[1];
    const int*   batch = (const int*)d_in[2];
    const float* c1W1  = (const float*)d_in[3];
    const float* c1b1  = (const float*)d_in[4];
    const float* c1W2  = (const float*)d_in[5];
    const float* c1b2  = (const float*)d_in[6];
    const float* c1g   = (const float*)d_in[7];
    const float* c1be  = (const float*)d_in[8];
    const float* c1m   = (const float*)d_in[9];
    const float* c1v   = (const float*)d_in[10];
    const float* c1e   = (const float*)d_in[11];
    const float* csW1  = (const float*)d_in[12];
    const float* csb1  = (const float*)d_in[13];
    const float* csW2  = (const float*)d_in[14];
    const float* csb2  = (const float*)d_in[15];
    const float* csg   = (const float*)d_in[16];
    const float* csbe  = (const float*)d_in[17];
    const float* csm   = (const float*)d_in[18];
    const float* csv   = (const float*)d_in[19];
    const float* cse   = (const float*)d_in[20];
    const float* l1W   = (const float*)d_in[21];
    const float* l1b   = (const float*)d_in[22];
    const float* l2W   = (const float*)d_in[23];
    const float* l2b   = (const float*)d_in[24];
    float* out = (float*)d_out;

    float* hF;
    __half *agg16, *x16, *h16A, *h16B;
    cudaGetSymbolAddress((void**)&agg16, g_agg16);
    cudaGetSymbolAddress((void**)&hF, g_hF);
    cudaGetSymbolAddress((void**)&x16, g_x16);
    cudaGetSymbolAddress((void**)&h16A, g_h16A);
    cudaGetSymbolAddress((void**)&h16B, g_h16B);

    const int SMEM_BYTES = MLP_SMEM_U32 * 4;  // 106,496 B (occ 2)
    cudaFuncSetAttribute(mlp_kernel, cudaFuncAttributeMaxDynamicSharedMemorySize,
                         SMEM_BYTES);

    const int IP_GRID   = 10 + (2 * NN + 255) / 256;
    const int X16_GRID  = (2 * NN * HH) / (8 * 256);  // 12.8M exact
    const int E_GRID    = (2 * EE + 255) / 256;
    const int AGG_GRID  = (2 * NN * 32 + 255) / 256;
    const dim3 MLP_GRID((NN + 127) / 128, 2);
    const int POOL_GRID = (2 * NN * 32 + 255) / 256;

    init_prep_kernel<<<IP_GRID, 256>>>(c1W1, c1W2, csW1, csW2);
    x16_kernel<<<X16_GRID, 256>>>(x);
    fill_kernel<<<E_GRID, 256>>>(ei);

    // layer 0 (conv1, per-ensemble weights: slots 0+ens / 2+ens) -> fp16 out
    agg_kernel<<<AGG_GRID, 256>>>(x16, agg16, c1e, 1);
    mlp_kernel<<<MLP_GRID, 256, SMEM_BYTES>>>(
        agg16, nullptr, h16A, 0, 1, 2, 1, c1b1, c1b2, c1g, c1be, c1m, c1v, 128);

    // layers 1..2 (shared weights: slots 4+l / 7+l) -> fp16 out
    const __half* cur = h16A;
    __half* nxt = h16B;
    for (int l = 0; l < 2; l++) {
        agg_kernel<<<AGG_GRID, 256>>>(cur, agg16, cse + l, 0);
        mlp_kernel<<<MLP_GRID, 256, SMEM_BYTES>>>(
            agg16, nullptr, nxt, 4 + l, 0, 7 + l, 0,
            csb1 + l * 128, csb2 + l * 128,
            csg + l * 128, csbe + l * 128, csm + l * 128, csv + l * 128, 0);
        const __half* tswap = cur;
        cur = nxt;
        nxt = (__half*)tswap;
    }

    // layer 3: fp32 out for pool
    agg_kernel<<<AGG_GRID, 256>>>(cur, agg16, cse + 2, 0);
    mlp_kernel<<<MLP_GRID, 256, SMEM_BYTES>>>(
        agg16, hF, nullptr, 6, 0, 9, 0,
        csb1 + 2 * 128, csb2 + 2 * 128,
        csg + 2 * 128, csbe + 2 * 128, csm + 2 * 128, csv + 2 * 128, 0);

    pool_kernel<<<POOL_GRID, 256>>>(hF, batch);
    head_kernel<<<dim3(GG, 2), 128>>>(l1W, l1b, l2W, l2b, out);
}

// round 14
// speedup vs baseline: 1.2033x; 1.0731x over previous
#include <cuda_runtime.h>
#include <cuda_bf16.h>
#include <cuda_fp16.h>
#include <math.h>
#include <stdint.h>

#define NN 50000
#define EE 800000
#define GG 128
#define HH 128
#define CC 10
#define BCAP 64   // per-node neighbor bucket capacity (max degree ~35)

// ---------------- scratch (__device__ globals; no allocs allowed) ------------
__device__ __half g_agg16[2][NN * HH];       // fp16 MLP input (agg output)
__device__ float g_hF[2][NN * HH];           // fp32 final-layer output (pool)
__device__ __half g_x16[2][NN * HH];         // fp16 copy of x for gather
__device__ __half g_h16A[2][NN * HH];        // fp16 inter-layer activations
__device__ __half g_h16B[2][NN * HH];
__device__ float g_pool[2][GG * HH];
__device__ float g_cnt[2][GG];
__device__ int g_bcnt[2][NN];
__device__ int g_bsrc[2][NN * BCAP];
// pre-split fp16 weights: [matrix][hi/lo][128n * 68u32]
// slots: 0,1 = c1W1 ens0/1 ; 2,3 = c1W2 ens0/1 ; 4..6 = csW1 l ; 7..9 = csW2 l
__device__ uint32_t g_wsplit[10][2][8704];

// ---------------- small helpers ----------------
__device__ __forceinline__ void hsplit(float v, __half& h, __half& l) {
    h = __float2half_rn(v);
    l = __float2half_rn(v - __half2float(h));
}

// fp16 MMA, fp32 accumulate
#define MMAF16(c, a0, a1, a2, a3, b0, b1)                                    \
    asm volatile(                                                            \
        "mma.sync.aligned.m16n8k16.row.col.f32.f16.f16.f32 "                 \
        "{%0,%1,%2,%3}, {%4,%5,%6,%7}, {%8,%9}, {%0,%1,%2,%3};"              \
        : "+f"(c[0]), "+f"(c[1]), "+f"(c[2]), "+f"(c[3])                     \
        : "r"(a0), "r"(a1), "r"(a2), "r"(a3), "r"(b0), "r"(b1))

// u32-as-half2 add
__device__ __forceinline__ uint32_t h2add(uint32_t a, uint32_t b) {
    __half2 r = __hadd2(*(__half2*)&a, *(__half2*)&b);
    return *(uint32_t*)&r;
}

// ------- merged init: blocks 0..9 pre-split weights; rest zero counters -----
__global__ void init_prep_kernel(const float* __restrict__ c1W1,
                                 const float* __restrict__ c1W2,
                                 const float* __restrict__ csW1,
                                 const float* __restrict__ csW2) {
    if (blockIdx.x < 10) {
        int b = blockIdx.x;
        const float* W;
        if (b < 2)       W = c1W1 + (size_t)b * 16384;
        else if (b < 4)  W = c1W2 + (size_t)(b - 2) * 16384;
        else if (b < 7)  W = csW1 + (size_t)(b - 4) * 16384;
        else             W = csW2 + (size_t)(b - 7) * 16384;
        __half* whb = (__half*)g_wsplit[b][0];
        __half* wlb = (__half*)g_wsplit[b][1];
        const float4* Wv = (const float4*)W;
        for (int idx = threadIdx.x; idx < 4096; idx += 256) {
            int k = idx >> 5, nq = idx & 31;
            float4 v = Wv[k * 32 + nq];
            float vv[4] = {v.x, v.y, v.z, v.w};
#pragma unroll
            for (int i = 0; i < 4; i++) {
                int n = 4 * nq + i;
                __half h, l;
                hsplit(vv[i], h, l);
                whb[n * 136 + k] = h;   // W^T: [n][k], stride 136 half (68 u32)
                wlb[n * 136 + k] = l;
            }
        }
    } else {
        int i = (blockIdx.x - 10) * 256 + threadIdx.x;
        if (i < 2 * NN) g_bcnt[0][i] = 0;          // contiguous [2][NN]
        if (i < 2 * GG * HH) g_pool[0][i] = 0.f;
        if (i < 2 * GG) g_cnt[0][i] = 0.f;
    }
}

// ---------------- x -> fp16 conversion (8 elems/thread) ----------------
__global__ void x16_kernel(const float* __restrict__ x) {
    size_t i = ((size_t)blockIdx.x * 256 + threadIdx.x) * 8;  // < 12.8M exact
    float4 a = *(const float4*)(x + i);
    float4 b = *(const float4*)(x + i + 4);
    __half2 h0 = __floats2half2_rn(a.x, a.y);
    __half2 h1 = __floats2half2_rn(a.z, a.w);
    __half2 h2 = __floats2half2_rn(b.x, b.y);
    __half2 h3 = __floats2half2_rn(b.z, b.w);
    uint4 o;
    o.x = *(uint32_t*)&h0; o.y = *(uint32_t*)&h1;
    o.z = *(uint32_t*)&h2; o.w = *(uint32_t*)&h3;
    *(uint4*)((__half*)g_x16 + i) = o;
}

// ---------------- bucket fill ----------------
__global__ void fill_kernel(const int* __restrict__ ei) {
    int idx = blockIdx.x * 256 + threadIdx.x;
    if (idx < 2 * EE) {
        int ens = idx >= EE;
        int e = idx - ens * EE;
        const int* base = ei + (size_t)ens * 2 * EE;
        int d = base[EE + e];
        int slot = atomicAdd(&g_bcnt[ens][d], 1);
        g_bsrc[ens][(size_t)d * BCAP + slot] = base[e];
    }
}

// 2 nodes per warp: half-warp per node, uint4 (16B) per lane.
// One warp LDG.128 gathers neighbor rows for BOTH nodes (512B/instr).
// agg[n] = (1+eps)*x[n] + sum_j x[j]; 2 HADD2 chains, fp32 combine.
__global__ __launch_bounds__(256, 6) void agg_kernel(
    const __half* __restrict__ xbase,
    __half* __restrict__ aggbase,
    const float* __restrict__ eps_p, int eps_stride) {
    unsigned idx = blockIdx.x * 256u + threadIdx.x;
    unsigned w = idx >> 5;
    unsigned lane = idx & 31u;
    unsigned g = 2u * w + (lane >> 4);   // global node id
    unsigned s = lane & 15u;             // 16B chunk (uint4) within 256B row
    if (g >= 2 * NN) return;
    int ens = g >= NN;
    unsigned n = g - (unsigned)ens * NN;
    float e1 = 1.0f + eps_p[ens * eps_stride];
    const uint4* xv = (const uint4*)(xbase + (size_t)ens * NN * HH);  // 16/row
    const int* __restrict__ bucket = &g_bsrc[ens][(size_t)n * BCAP];
    const int4* __restrict__ b4 = (const int4*)bucket;  // 256B-aligned rows
    int deg = g_bcnt[ens][n];

    uint32_t A0 = 0, A1 = 0, A2 = 0, A3 = 0;   // chain A (4 half2)
    uint32_t B0 = 0, B1 = 0, B2 = 0, B3 = 0;   // chain B

    uint4 self = __ldg(&xv[(size_t)n * 16 + s]);

    int e = 0;
    for (; e + 4 <= deg; e += 4) {
        int4 ia = __ldg(&b4[e >> 2]);
        uint4 p0 = __ldg(&xv[(size_t)(unsigned)ia.x * 16 + s]);
        uint4 p1 = __ldg(&xv[(size_t)(unsigned)ia.y * 16 + s]);
        uint4 p2 = __ldg(&xv[(size_t)(unsigned)ia.z * 16 + s]);
        uint4 p3 = __ldg(&xv[(size_t)(unsigned)ia.w * 16 + s]);
        A0 = h2add(A0, p0.x); A1 = h2add(A1, p0.y);
        A2 = h2add(A2, p0.z); A3 = h2add(A3, p0.w);
        B0 = h2add(B0, p1.x); B1 = h2add(B1, p1.y);
        B2 = h2add(B2, p1.z); B3 = h2add(B3, p1.w);
        A0 = h2add(A0, p2.x); A1 = h2add(A1, p2.y);
        A2 = h2add(A2, p2.z); A3 = h2add(A3, p2.w);
        B0 = h2add(B0, p3.x); B1 = h2add(B1, p3.y);
        B2 = h2add(B2, p3.z); B3 = h2add(B3, p3.w);
    }
    for (; e < deg; e++) {
        int sn = __ldg(&bucket[e]);
        uint4 p = __ldg(&xv[(size_t)(unsigned)sn * 16 + s]);
        if (e & 1) {
            B0 = h2add(B0, p.x); B1 = h2add(B1, p.y);
            B2 = h2add(B2, p.z); B3 = h2add(B3, p.w);
        } else {
            A0 = h2add(A0, p.x); A1 = h2add(A1, p.y);
            A2 = h2add(A2, p.z); A3 = h2add(A3, p.w);
        }
    }

    // combine 2 chains + (1+eps)*self in fp32, per 32-bit word
    uint4 o;
    uint32_t ca[4] = {A0, A1, A2, A3};
    uint32_t cb[4] = {B0, B1, B2, B3};
    uint32_t sv[4] = {self.x, self.y, self.z, self.w};
    uint32_t ov[4];
#pragma unroll
    for (int k = 0; k < 4; k++) {
        float2 fa = __half22float2(*(__half2*)&ca[k]);
        float2 fb = __half22float2(*(__half2*)&cb[k]);
        float2 fs = __half22float2(*(__half2*)&sv[k]);
        float rx = fa.x + fb.x + e1 * fs.x;
        float ry = fa.y + fb.y + e1 * fs.y;
        __half2 r = __floats2half2_rn(rx, ry);
        ov[k] = *(uint32_t*)&r;
    }
    o.x = ov[0]; o.y = ov[1]; o.z = ov[2]; o.w = ov[3];
    ((uint4*)(aggbase + (size_t)ens * NN * HH))[(size_t)n * 16 + s] = o;
}

// ---------------- MLP: fp16 A + fp16-split W, mma.sync, occ 2 ---------------
// smem u32: As[8704] WH[8704] WL[8704] prm[512] = 26624 u32 (106.5KB)
#define MLP_SMEM_U32 26624

__device__ __forceinline__ void copy_w(const uint32_t* __restrict__ gh,
                                       const uint32_t* __restrict__ gl,
                                       uint32_t* wh, uint32_t* wl, int tid) {
    const uint4* gh4 = (const uint4*)gh;
    const uint4* gl4 = (const uint4*)gl;
    uint4* wh4 = (uint4*)wh;
    uint4* wl4 = (uint4*)wl;
    for (int i = tid; i < 2176; i += 256) {
        wh4[i] = gh4[i];
        wl4[i] = gl4[i];
    }
}

// 32x64 warp tile: rows r0+16*rs (+8), cols nbase + 8j + ...
__device__ __forceinline__ void do_gemm(const uint32_t* __restrict__ As,
                                        const uint32_t* __restrict__ WH,
                                        const uint32_t* __restrict__ WL,
                                        int r0, int nbase, int tg, int tp,
                                        float acc[2][8][4]) {
#pragma unroll
    for (int c = 0; c < 8; c++) {
        int ko = tp + 8 * c;
        uint32_t ah[2][4];
#pragma unroll
        for (int rs = 0; rs < 2; rs++) {
            int ar = (r0 + 16 * rs) * 68;
            int ar8 = ar + 8 * 68;
            ah[rs][0] = As[ar + ko];      ah[rs][1] = As[ar8 + ko];
            ah[rs][2] = As[ar + ko + 4];  ah[rs][3] = As[ar8 + ko + 4];
        }
#pragma unroll
        for (int j = 0; j < 8; j++) {
            int nb = (nbase + 8 * j + tg) * 68 + ko;
            uint32_t bh0 = WH[nb], bh1 = WH[nb + 4];
            uint32_t bl0 = WL[nb], bl1 = WL[nb + 4];
#pragma unroll
            for (int rs = 0; rs < 2; rs++) {
                MMAF16(acc[rs][j], ah[rs][0], ah[rs][1], ah[rs][2], ah[rs][3], bh0, bh1);
                MMAF16(acc[rs][j], ah[rs][0], ah[rs][1], ah[rs][2], ah[rs][3], bl0, bl1);
            }
        }
    }
}

__global__ __launch_bounds__(256, 2) void mlp_kernel(
    const __half* __restrict__ Abase, float* __restrict__ outbase,
    __half* __restrict__ out16base,
    int w1slot, int w1stride, int w2slot, int w2stride,
    const float* __restrict__ b1, const float* __restrict__ b2,
    const float* __restrict__ gamma, const float* __restrict__ beta,
    const float* __restrict__ mean, const float* __restrict__ var, int vs) {
    extern __shared__ uint32_t sm32[];
    uint32_t* As = sm32;
    uint32_t* WH = sm32 + 8704;
    uint32_t* WL = sm32 + 17408;
    float* b1s = (float*)(sm32 + 26112);
    float* b2s = b1s + 128;
    float* scs = b2s + 128;
    float* shs = scs + 128;

    int ens = blockIdx.y;
    const __half* A = Abase + (size_t)ens * NN * HH;
    b1 += ens * vs;  b2 += ens * vs;
    gamma += ens * vs;  beta += ens * vs;  mean += ens * vs;  var += ens * vs;
    int s1 = w1slot + ens * w1stride;
    int s2 = w2slot + ens * w2stride;

    int tid = threadIdx.x;
    int wid = tid >> 5, t = tid & 31, tg = t >> 2, tp = t & 3;
    int wm = wid & 3, wcol = wid >> 2;
    int rb = blockIdx.x * 128;

    if (tid < 128) {
        b1s[tid] = b1[tid];
        b2s[tid] = b2[tid];
        float sc = gamma[tid] * rsqrtf(var[tid] + 1e-5f);
        scs[tid] = sc;
        shs[tid] = beta[tid] - mean[tid] * sc;
    }

    // stage A tile (128 rows x 128 halves), pure copy
    {
        const uint2* Av = (const uint2*)A;  // 32 uint2 per row
        uint2* As2 = (uint2*)As;            // stride 34 uint2
        for (int idx = tid; idx < 4096; idx += 256) {
            int r = idx >> 5, q = idx & 31;
            int gr = rb + r;
            uint2 v = (gr < NN) ? Av[(size_t)gr * 32 + q] : make_uint2(0u, 0u);
            As2[r * 34 + q] = v;
        }
    }
    copy_w(g_wsplit[s1][0], g_wsplit[s1][1], WH, WL, tid);
    __syncthreads();

    float acc[2][8][4];
#pragma unroll
    for (int rs = 0; rs < 2; rs++)
#pragma unroll
        for (int j = 0; j < 8; j++)
#pragma unroll
            for (int q = 0; q < 4; q++) acc[rs][j][q] = 0.f;

    int r0 = wm * 32 + tg;
    int nbase = wcol * 64;

    do_gemm(As, WH, WL, r0, nbase, tg, tp, acc);
    __syncthreads();

    // epilogue 1: h1 = relu(acc + b1) -> fp16 back into As (own rows/cols)
#pragma unroll
    for (int rs = 0; rs < 2; rs++) {
        int arow = (r0 + 16 * rs) * 68;
        int arow8 = arow + 8 * 68;
#pragma unroll
        for (int j = 0; j < 8; j++) {
            int col0 = nbase + 8 * j + 2 * tp;
            int cu = col0 >> 1;
            float bb0 = b1s[col0], bb1 = b1s[col0 + 1];
            float v0 = fmaxf(acc[rs][j][0] + bb0, 0.f);
            float v1 = fmaxf(acc[rs][j][1] + bb1, 0.f);
            float v2 = fmaxf(acc[rs][j][2] + bb0, 0.f);
            float v3 = fmaxf(acc[rs][j][3] + bb1, 0.f);
            __half2 p0 = __floats2half2_rn(v0, v1);
            __half2 p1 = __floats2half2_rn(v2, v3);
            As[arow + cu] = *(uint32_t*)&p0;
            As[arow8 + cu] = *(uint32_t*)&p1;
            acc[rs][j][0] = acc[rs][j][1] = acc[rs][j][2] = acc[rs][j][3] = 0.f;
        }
    }
    copy_w(g_wsplit[s2][0], g_wsplit[s2][1], WH, WL, tid);
    __syncthreads();

    do_gemm(As, WH, WL, r0, nbase, tg, tp, acc);

    // final epilogue: relu -> BN -> relu -> global (fp16 or fp32)
#pragma unroll
    for (int rs = 0; rs < 2; rs++) {
        int gr0 = rb + r0 + 16 * rs;
        int gr8 = gr0 + 8;
#pragma unroll
        for (int j = 0; j < 8; j++) {
            int col0 = nbase + 8 * j + 2 * tp;
            float bb0 = b2s[col0], bb1 = b2s[col0 + 1];
            float s0 = scs[col0], s1f = scs[col0 + 1];
            float t0 = shs[col0], t1 = shs[col0 + 1];
            float v0 = fmaxf(acc[rs][j][0] + bb0, 0.f);
            float v1 = fmaxf(acc[rs][j][1] + bb1, 0.f);
            float v2 = fmaxf(acc[rs][j][2] + bb0, 0.f);
            float v3 = fmaxf(acc[rs][j][3] + bb1, 0.f);
            float o0 = fmaxf(v0 * s0 + t0, 0.f);
            float o1 = fmaxf(v1 * s1f + t1, 0.f);
            float o2 = fmaxf(v2 * s0 + t0, 0.f);
            float o3 = fmaxf(v3 * s1f + t1, 0.f);
            if (out16base) {
                __half* o16 = out16base + (size_t)ens * NN * HH;
                if (gr0 < NN)
                    *(__half2*)(o16 + (size_t)gr0 * HH + col0) = __floats2half2_rn(o0, o1);
                if (gr8 < NN)
                    *(__half2*)(o16 + (size_t)gr8 * HH + col0) = __floats2half2_rn(o2, o3);
            } else {
                float* out = outbase + (size_t)ens * NN * HH;
                if (gr0 < NN)
                    *(float2*)(out + (size_t)gr0 * HH + col0) = make_float2(o0, o1);
                if (gr8 < NN)
                    *(float2*)(out + (size_t)gr8 * HH + col0) = make_float2(o2, o3);
            }
        }
    }
}

// ---------------- pool + head ----------------
__global__ void pool_kernel(const float* __restrict__ hbase,
                            const int* __restrict__ batch) {
    unsigned idx = blockIdx.x * 256u + threadIdx.x;
    unsigned wn = idx >> 5;
    unsigned c = (idx & 31u) << 2;
    if (wn >= 2 * NN) return;
    int ens = wn >= NN;
    unsigned n = wn - (unsigned)ens * NN;
    int g = batch[(size_t)ens * NN + n];
    const float* h = hbase + (size_t)ens * NN * HH;
    float4 v = *(const float4*)(h + (size_t)n * HH + c);
    atomicAdd((float4*)(&g_pool[ens][g * HH + c]), v);
    if (c == 0) atomicAdd(&g_cnt[ens][g], 1.0f);
}

__global__ void head_kernel(const float* __restrict__ W1all,
                            const float* __restrict__ b1all,
                            const float* __restrict__ W2all,
                            const float* __restrict__ b2all,
                            float* __restrict__ out) {
    int g = blockIdx.x;
    int ens = blockIdx.y;
    int c = threadIdx.x;  // 128 threads
    const float* W1 = W1all + (size_t)ens * 16384;
    const float* b1 = b1all + ens * 128;
    const float* W2 = W2all + (size_t)ens * 1280;
    const float* b2 = b2all + ens * 10;
    __shared__ float p[128];
    __shared__ float z[128];
    float cn = fmaxf(g_cnt[ens][g], 1.0f);
    p[c] = g_pool[ens][g * HH + c] / cn;
    __syncthreads();
    float acc = b1[c];
#pragma unroll 4
    for (int k = 0; k < 128; k++) acc += p[k] * W1[k * 128 + c];
    z[c] = fmaxf(acc, 0.f);
    __syncthreads();
    if (c < CC) {
        float y = b2[c];
#pragma unroll 4
        for (int k = 0; k < 128; k++) y += z[k] * W2[k * CC + c];
        out[((size_t)ens * GG + g) * CC + c] = y;
    }
}

// ---------------- driver ----------------
extern "C" void kernel_launch(void* const* d_in, const int* in_sizes, int n_in,
                              void* d_out, int out_size) {
    const float* x     = (const float*)d_in[0];
    const int*   ei    = (const int*)d_in[1];
    const int*   batch = (const int*)d_in[2];
    const float* c1W1  = (const float*)d_in[3];
    const float* c1b1  = (const float*)d_in[4];
    const float* c1W2  = (const float*)d_in[5];
    const float* c1b2  = (const float*)d_in[6];
    const float* c1g   = (const float*)d_in[7];
    const float* c1be  = (const float*)d_in[8];
    const float* c1m   = (const float*)d_in[9];
    const float* c1v   = (const float*)d_in[10];
    const float* c1e   = (const float*)d_in[11];
    const float* csW1  = (const float*)d_in[12];
    const float* csb1  = (const float*)d_in[13];
    const float* csW2  = (const float*)d_in[14];
    const float* csb2  = (const float*)d_in[15];
    const float* csg   = (const float*)d_in[16];
    const float* csbe  = (const float*)d_in[17];
    const float* csm   = (const float*)d_in[18];
    const float* csv   = (const float*)d_in[19];
    const float* cse   = (const float*)d_in[20];
    const float* l1W   = (const float*)d_in[21];
    const float* l1b   = (const float*)d_in[22];
    const float* l2W   = (const float*)d_in[23];
    const float* l2b   = (const float*)d_in[24];
    float* out = (float*)d_out;

    float* hF;
    __half *agg16, *x16, *h16A, *h16B;
    cudaGetSymbolAddress((void**)&agg16, g_agg16);
    cudaGetSymbolAddress((void**)&hF, g_hF);
    cudaGetSymbolAddress((void**)&x16, g_x16);
    cudaGetSymbolAddress((void**)&h16A, g_h16A);
    cudaGetSymbolAddress((void**)&h16B, g_h16B);

    const int SMEM_BYTES = MLP_SMEM_U32 * 4;  // 106,496 B (occ 2)
    cudaFuncSetAttribute(mlp_kernel, cudaFuncAttributeMaxDynamicSharedMemorySize,
                         SMEM_BYTES);

    const int IP_GRID   = 10 + (2 * NN + 255) / 256;
    const int X16_GRID  = (2 * NN * HH) / (8 * 256);  // 12.8M exact
    const int E_GRID    = (2 * EE + 255) / 256;
    const int AGG_GRID  = (NN * 32 + 255) / 256;      // 2 nodes/warp
    const dim3 MLP_GRID((NN + 127) / 128, 2);
    const int POOL_GRID = (2 * NN * 32 + 255) / 256;

    init_prep_kernel<<<IP_GRID, 256>>>(c1W1, c1W2, csW1, csW2);
    x16_kernel<<<X16_GRID, 256>>>(x);
    fill_kernel<<<E_GRID, 256>>>(ei);

    // layer 0 (conv1, per-ensemble weights: slots 0+ens / 2+ens) -> fp16 out
    agg_kernel<<<AGG_GRID, 256>>>(x16, agg16, c1e, 1);
    mlp_kernel<<<MLP_GRID, 256, SMEM_BYTES>>>(
        agg16, nullptr, h16A, 0, 1, 2, 1, c1b1, c1b2, c1g, c1be, c1m, c1v, 128);

    // layers 1..2 (shared weights: slots 4+l / 7+l) -> fp16 out
    const __half* cur = h16A;
    __half* nxt = h16B;
    for (int l = 0; l < 2; l++) {
        agg_kernel<<<AGG_GRID, 256>>>(cur, agg16, cse + l, 0);
        mlp_kernel<<<MLP_GRID, 256, SMEM_BYTES>>>(
            agg16, nullptr, nxt, 4 + l, 0, 7 + l, 0,
            csb1 + l * 128, csb2 + l * 128,
            csg + l * 128, csbe + l * 128, csm + l * 128, csv + l * 128, 0);
        const __half* tswap = cur;
        cur = nxt;
        nxt = (__half*)tswap;
    }

    // layer 3: fp32 out for pool
    agg_kernel<<<AGG_GRID, 256>>>(cur, agg16, cse + 2, 0);
    mlp_kernel<<<MLP_GRID, 256, SMEM_BYTES>>>(
        agg16, hF, nullptr, 6, 0, 9, 0,
        csb1 + 2 * 128, csb2 + 2 * 128,
        csg + 2 * 128, csbe + 2 * 128, csm + 2 * 128, csv + 2 * 128, 0);

    pool_kernel<<<POOL_GRID, 256>>>(hF, batch);
    head_kernel<<<dim3(GG, 2), 128>>>(l1W, l1b, l2W, l2b, out);
}

// round 15
// speedup vs baseline: 1.2127x; 1.0078x over previous
#include <cuda_runtime.h>
#include <cuda_bf16.h>
#include <cuda_fp16.h>
#include <math.h>
#include <stdint.h>

#define NN 50000
#define EE 800000
#define GG 128
#define HH 128
#define CC 10
#define BCAP 64   // per-node neighbor bucket capacity (max degree ~35)

// ---------------- scratch (__device__ globals; no allocs allowed) ------------
__device__ __half g_agg16[2][NN * HH];       // fp16 MLP input (agg output)
__device__ float g_hF[2][NN * HH];           // fp32 final-layer output (pool)
__device__ __half g_x16[2][NN * HH];         // fp16 copy of x for gather
__device__ __half g_h16A[2][NN * HH];        // fp16 inter-layer activations
__device__ __half g_h16B[2][NN * HH];
__device__ float g_pool[2][GG * HH];
__device__ float g_cnt[2][GG];
__device__ int g_bcnt[2][NN];
__device__ int g_bsrc[2][NN * BCAP];
// pre-split fp16 weights: [matrix][hi/lo][128n * 68u32]
// slots: 0,1 = c1W1 ens0/1 ; 2,3 = c1W2 ens0/1 ; 4..6 = csW1 l ; 7..9 = csW2 l
__device__ uint32_t g_wsplit[10][2][8704];

// ---------------- small helpers ----------------
__device__ __forceinline__ void hsplit(float v, __half& h, __half& l) {
    h = __float2half_rn(v);
    l = __float2half_rn(v - __half2float(h));
}

// fp16 MMA, fp32 accumulate
#define MMAF16(c, a0, a1, a2, a3, b0, b1)                                    \
    asm volatile(                                                            \
        "mma.sync.aligned.m16n8k16.row.col.f32.f16.f16.f32 "                 \
        "{%0,%1,%2,%3}, {%4,%5,%6,%7}, {%8,%9}, {%0,%1,%2,%3};"              \
        : "+f"(c[0]), "+f"(c[1]), "+f"(c[2]), "+f"(c[3])                     \
        : "r"(a0), "r"(a1), "r"(a2), "r"(a3), "r"(b0), "r"(b1))

// u32-as-half2 add
__device__ __forceinline__ uint32_t h2add(uint32_t a, uint32_t b) {
    __half2 r = __hadd2(*(__half2*)&a, *(__half2*)&b);
    return *(uint32_t*)&r;
}

// ------- merged init: weight pre-split + zero counters + x->fp16 -----------
// blocks [0,10): weight split; [10, 10+ZB): zeroing; [10+ZB, ...): x16 convert
#define ZB ((2 * NN + 255) / 256)
#define XB ((2 * NN * HH) / (8 * 256))
__global__ void init_prep_kernel(const float* __restrict__ c1W1,
                                 const float* __restrict__ c1W2,
                                 const float* __restrict__ csW1,
                                 const float* __restrict__ csW2,
                                 const float* __restrict__ x) {
    if (blockIdx.x < 10) {
        int b = blockIdx.x;
        const float* W;
        if (b < 2)       W = c1W1 + (size_t)b * 16384;
        else if (b < 4)  W = c1W2 + (size_t)(b - 2) * 16384;
        else if (b < 7)  W = csW1 + (size_t)(b - 4) * 16384;
        else             W = csW2 + (size_t)(b - 7) * 16384;
        __half* whb = (__half*)g_wsplit[b][0];
        __half* wlb = (__half*)g_wsplit[b][1];
        const float4* Wv = (const float4*)W;
        for (int idx = threadIdx.x; idx < 4096; idx += 256) {
            int k = idx >> 5, nq = idx & 31;
            float4 v = Wv[k * 32 + nq];
            float vv[4] = {v.x, v.y, v.z, v.w};
#pragma unroll
            for (int i = 0; i < 4; i++) {
                int n = 4 * nq + i;
                __half h, l;
                hsplit(vv[i], h, l);
                whb[n * 136 + k] = h;   // W^T: [n][k], stride 136 half (68 u32)
                wlb[n * 136 + k] = l;
            }
        }
    } else if (blockIdx.x < 10 + ZB) {
        int i = (blockIdx.x - 10) * 256 + threadIdx.x;
        if (i < 2 * NN) g_bcnt[0][i] = 0;          // contiguous [2][NN]
        if (i < 2 * GG * HH) g_pool[0][i] = 0.f;
        if (i < 2 * GG) g_cnt[0][i] = 0.f;
    } else {
        size_t i = ((size_t)(blockIdx.x - 10 - ZB) * 256 + threadIdx.x) * 8;
        float4 a = *(const float4*)(x + i);
        float4 b = *(const float4*)(x + i + 4);
        __half2 h0 = __floats2half2_rn(a.x, a.y);
        __half2 h1 = __floats2half2_rn(a.z, a.w);
        __half2 h2 = __floats2half2_rn(b.x, b.y);
        __half2 h3 = __floats2half2_rn(b.z, b.w);
        uint4 o;
        o.x = *(uint32_t*)&h0; o.y = *(uint32_t*)&h1;
        o.z = *(uint32_t*)&h2; o.w = *(uint32_t*)&h3;
        *(uint4*)((__half*)g_x16 + i) = o;
    }
}

// ---------------- bucket fill: 4 edges/thread via int4 ----------------
__global__ void fill_kernel(const int* __restrict__ ei) {
    int q = blockIdx.x * 256 + threadIdx.x;      // quad index over 2*EE/4
    if (q >= 2 * (EE / 4)) return;
    int ens = q >= (EE / 4);
    int e4 = q - ens * (EE / 4);
    const int* base = ei + (size_t)ens * 2 * EE;
    int4 s4 = __ldg((const int4*)(base) + e4);
    int4 d4 = __ldg((const int4*)(base + EE) + e4);
    int* bc = g_bcnt[ens];
    int* bs = g_bsrc[ens];
    int slot;
    slot = atomicAdd(&bc[d4.x], 1); bs[(size_t)d4.x * BCAP + slot] = s4.x;
    slot = atomicAdd(&bc[d4.y], 1); bs[(size_t)d4.y * BCAP + slot] = s4.y;
    slot = atomicAdd(&bc[d4.z], 1); bs[(size_t)d4.z * BCAP + slot] = s4.z;
    slot = atomicAdd(&bc[d4.w], 1); bs[(size_t)d4.w * BCAP + slot] = s4.w;
}

// 2 nodes per warp: half-warp per node, uint4 (16B) per lane.
__global__ __launch_bounds__(256, 6) void agg_kernel(
    const __half* __restrict__ xbase,
    __half* __restrict__ aggbase,
    const float* __restrict__ eps_p, int eps_stride) {
    unsigned idx = blockIdx.x * 256u + threadIdx.x;
    unsigned w = idx >> 5;
    unsigned lane = idx & 31u;
    unsigned g = 2u * w + (lane >> 4);   // global node id
    unsigned s = lane & 15u;             // 16B chunk (uint4) within 256B row
    if (g >= 2 * NN) return;
    int ens = g >= NN;
    unsigned n = g - (unsigned)ens * NN;
    float e1 = 1.0f + eps_p[ens * eps_stride];
    const uint4* xv = (const uint4*)(xbase + (size_t)ens * NN * HH);  // 16/row
    const int* __restrict__ bucket = &g_bsrc[ens][(size_t)n * BCAP];
    const int4* __restrict__ b4 = (const int4*)bucket;  // 256B-aligned rows
    int deg = g_bcnt[ens][n];

    uint32_t A0 = 0, A1 = 0, A2 = 0, A3 = 0;   // chain A (4 half2)
    uint32_t B0 = 0, B1 = 0, B2 = 0, B3 = 0;   // chain B

    uint4 self = __ldg(&xv[(size_t)n * 16 + s]);

    int e = 0;
    for (; e + 4 <= deg; e += 4) {
        int4 ia = __ldg(&b4[e >> 2]);
        uint4 p0 = __ldg(&xv[(size_t)(unsigned)ia.x * 16 + s]);
        uint4 p1 = __ldg(&xv[(size_t)(unsigned)ia.y * 16 + s]);
        uint4 p2 = __ldg(&xv[(size_t)(unsigned)ia.z * 16 + s]);
        uint4 p3 = __ldg(&xv[(size_t)(unsigned)ia.w * 16 + s]);
        A0 = h2add(A0, p0.x); A1 = h2add(A1, p0.y);
        A2 = h2add(A2, p0.z); A3 = h2add(A3, p0.w);
        B0 = h2add(B0, p1.x); B1 = h2add(B1, p1.y);
        B2 = h2add(B2, p1.z); B3 = h2add(B3, p1.w);
        A0 = h2add(A0, p2.x); A1 = h2add(A1, p2.y);
        A2 = h2add(A2, p2.z); A3 = h2add(A3, p2.w);
        B0 = h2add(B0, p3.x); B1 = h2add(B1, p3.y);
        B2 = h2add(B2, p3.z); B3 = h2add(B3, p3.w);
    }
    for (; e < deg; e++) {
        int sn = __ldg(&bucket[e]);
        uint4 p = __ldg(&xv[(size_t)(unsigned)sn * 16 + s]);
        if (e & 1) {
            B0 = h2add(B0, p.x); B1 = h2add(B1, p.y);
            B2 = h2add(B2, p.z); B3 = h2add(B3, p.w);
        } else {
            A0 = h2add(A0, p.x); A1 = h2add(A1, p.y);
            A2 = h2add(A2, p.z); A3 = h2add(A3, p.w);
        }
    }

    // combine 2 chains + (1+eps)*self in fp32, per 32-bit word
    uint4 o;
    uint32_t ca[4] = {A0, A1, A2, A3};
    uint32_t cb[4] = {B0, B1, B2, B3};
    uint32_t sv[4] = {self.x, self.y, self.z, self.w};
    uint32_t ov[4];
#pragma unroll
    for (int k = 0; k < 4; k++) {
        float2 fa = __half22float2(*(__half2*)&ca[k]);
        float2 fb = __half22float2(*(__half2*)&cb[k]);
        float2 fs = __half22float2(*(__half2*)&sv[k]);
        float rx = fa.x + fb.x + e1 * fs.x;
        float ry = fa.y + fb.y + e1 * fs.y;
        __half2 r = __floats2half2_rn(rx, ry);
        ov[k] = *(uint32_t*)&r;
    }
    o.x = ov[0]; o.y = ov[1]; o.z = ov[2]; o.w = ov[3];
    ((uint4*)(aggbase + (size_t)ens * NN * HH))[(size_t)n * 16 + s] = o;
}

// ---------------- MLP: fp16 A + fp16-split W, mma.sync, occ 2 ---------------
// smem u32: As[8704] WH[8704] WL[8704] prm[512] = 26624 u32 (106.5KB)
#define MLP_SMEM_U32 26624

__device__ __forceinline__ void copy_w(const uint32_t* __restrict__ gh,
                                       const uint32_t* __restrict__ gl,
                                       uint32_t* wh, uint32_t* wl, int tid) {
    const uint4* gh4 = (const uint4*)gh;
    const uint4* gl4 = (const uint4*)gl;
    uint4* wh4 = (uint4*)wh;
    uint4* wl4 = (uint4*)wl;
    for (int i = tid; i < 2176; i += 256) {
        wh4[i] = gh4[i];
        wl4[i] = gl4[i];
    }
}

// 32x64 warp tile: rows r0+16*rs (+8), cols nbase + 8j + ...
__device__ __forceinline__ void do_gemm(const uint32_t* __restrict__ As,
                                        const uint32_t* __restrict__ WH,
                                        const uint32_t* __restrict__ WL,
                                        int r0, int nbase, int tg, int tp,
                                        float acc[2][8][4]) {
#pragma unroll
    for (int c = 0; c < 8; c++) {
        int ko = tp + 8 * c;
        uint32_t ah[2][4];
#pragma unroll
        for (int rs = 0; rs < 2; rs++) {
            int ar = (r0 + 16 * rs) * 68;
            int ar8 = ar + 8 * 68;
            ah[rs][0] = As[ar + ko];      ah[rs][1] = As[ar8 + ko];
            ah[rs][2] = As[ar + ko + 4];  ah[rs][3] = As[ar8 + ko + 4];
        }
#pragma unroll
        for (int j = 0; j < 8; j++) {
            int nb = (nbase + 8 * j + tg) * 68 + ko;
            uint32_t bh0 = WH[nb], bh1 = WH[nb + 4];
            uint32_t bl0 = WL[nb], bl1 = WL[nb + 4];
#pragma unroll
            for (int rs = 0; rs < 2; rs++) {
                MMAF16(acc[rs][j], ah[rs][0], ah[rs][1], ah[rs][2], ah[rs][3], bh0, bh1);
                MMAF16(acc[rs][j], ah[rs][0], ah[rs][1], ah[rs][2], ah[rs][3], bl0, bl1);
            }
        }
    }
}

__global__ __launch_bounds__(256, 2) void mlp_kernel(
    const __half* __restrict__ Abase, float* __restrict__ outbase,
    __half* __restrict__ out16base,
    int w1slot, int w1stride, int w2slot, int w2stride,
    const float* __restrict__ b1, const float* __restrict__ b2,
    const float* __restrict__ gamma, const float* __restrict__ beta,
    const float* __restrict__ mean, const float* __restrict__ var, int vs) {
    extern __shared__ uint32_t sm32[];
    uint32_t* As = sm32;
    uint32_t* WH = sm32 + 8704;
    uint32_t* WL = sm32 + 17408;
    float* b1s = (float*)(sm32 + 26112);
    float* b2s = b1s + 128;
    float* scs = b2s + 128;
    float* shs = scs + 128;

    int ens = blockIdx.y;
    const __half* A = Abase + (size_t)ens * NN * HH;
    b1 += ens * vs;  b2 += ens * vs;
    gamma += ens * vs;  beta += ens * vs;  mean += ens * vs;  var += ens * vs;
    int s1 = w1slot + ens * w1stride;
    int s2 = w2slot + ens * w2stride;

    int tid = threadIdx.x;
    int wid = tid >> 5, t = tid & 31, tg = t >> 2, tp = t & 3;
    int wm = wid & 3, wcol = wid >> 2;
    int rb = blockIdx.x * 128;

    if (tid < 128) {
        b1s[tid] = b1[tid];
        b2s[tid] = b2[tid];
        float sc = gamma[tid] * rsqrtf(var[tid] + 1e-5f);
        scs[tid] = sc;
        shs[tid] = beta[tid] - mean[tid] * sc;
    }

    // stage A tile (128 rows x 128 halves), pure copy
    {
        const uint2* Av = (const uint2*)A;  // 32 uint2 per row
        uint2* As2 = (uint2*)As;            // stride 34 uint2
        for (int idx = tid; idx < 4096; idx += 256) {
            int r = idx >> 5, q = idx & 31;
            int gr = rb + r;
            uint2 v = (gr < NN) ? Av[(size_t)gr * 32 + q] : make_uint2(0u, 0u);
            As2[r * 34 + q] = v;
        }
    }
    copy_w(g_wsplit[s1][0], g_wsplit[s1][1], WH, WL, tid);
    __syncthreads();

    float acc[2][8][4];
#pragma unroll
    for (int rs = 0; rs < 2; rs++)
#pragma unroll
        for (int j = 0; j < 8; j++)
#pragma unroll
            for (int q = 0; q < 4; q++) acc[rs][j][q] = 0.f;

    int r0 = wm * 32 + tg;
    int nbase = wcol * 64;

    do_gemm(As, WH, WL, r0, nbase, tg, tp, acc);
    __syncthreads();

    // W1 is dead; start W2 copy FIRST so its L2 latency overlaps epilogue math
    copy_w(g_wsplit[s2][0], g_wsplit[s2][1], WH, WL, tid);

    // epilogue 1: h1 = relu(acc + b1) -> fp16 back into As (own rows/cols)
#pragma unroll
    for (int rs = 0; rs < 2; rs++) {
        int arow = (r0 + 16 * rs) * 68;
        int arow8 = arow + 8 * 68;
#pragma unroll
        for (int j = 0; j < 8; j++) {
            int col0 = nbase + 8 * j + 2 * tp;
            int cu = col0 >> 1;
            float bb0 = b1s[col0], bb1 = b1s[col0 + 1];
            float v0 = fmaxf(acc[rs][j][0] + bb0, 0.f);
            float v1 = fmaxf(acc[rs][j][1] + bb1, 0.f);
            float v2 = fmaxf(acc[rs][j][2] + bb0, 0.f);
            float v3 = fmaxf(acc[rs][j][3] + bb1, 0.f);
            __half2 p0 = __floats2half2_rn(v0, v1);
            __half2 p1 = __floats2half2_rn(v2, v3);
            As[arow + cu] = *(uint32_t*)&p0;
            As[arow8 + cu] = *(uint32_t*)&p1;
            acc[rs][j][0] = acc[rs][j][1] = acc[rs][j][2] = acc[rs][j][3] = 0.f;
        }
    }
    __syncthreads();

    do_gemm(As, WH, WL, r0, nbase, tg, tp, acc);

    // final epilogue: relu -> BN -> relu -> global (fp16 or fp32)
#pragma unroll
    for (int rs = 0; rs < 2; rs++) {
        int gr0 = rb + r0 + 16 * rs;
        int gr8 = gr0 + 8;
#pragma unroll
        for (int j = 0; j < 8; j++) {
            int col0 = nbase + 8 * j + 2 * tp;
            float bb0 = b2s[col0], bb1 = b2s[col0 + 1];
            float s0 = scs[col0], s1f = scs[col0 + 1];
            float t0 = shs[col0], t1 = shs[col0 + 1];
            float v0 = fmaxf(acc[rs][j][0] + bb0, 0.f);
            float v1 = fmaxf(acc[rs][j][1] + bb1, 0.f);
            float v2 = fmaxf(acc[rs][j][2] + bb0, 0.f);
            float v3 = fmaxf(acc[rs][j][3] + bb1, 0.f);
            float o0 = fmaxf(v0 * s0 + t0, 0.f);
            float o1 = fmaxf(v1 * s1f + t1, 0.f);
            float o2 = fmaxf(v2 * s0 + t0, 0.f);
            float o3 = fmaxf(v3 * s1f + t1, 0.f);
            if (out16base) {
                __half* o16 = out16base + (size_t)ens * NN * HH;
                if (gr0 < NN)
                    *(__half2*)(o16 + (size_t)gr0 * HH + col0) = __floats2half2_rn(o0, o1);
                if (gr8 < NN)
                    *(__half2*)(o16 + (size_t)gr8 * HH + col0) = __floats2half2_rn(o2, o3);
            } else {
                float* out = outbase + (size_t)ens * NN * HH;
                if (gr0 < NN)
                    *(float2*)(out + (size_t)gr0 * HH + col0) = make_float2(o0, o1);
                if (gr8 < NN)
                    *(float2*)(out + (size_t)gr8 * HH + col0) = make_float2(o2, o3);
            }
        }
    }
}

// ---------------- pool + head ----------------
__global__ void pool_kernel(const float* __restrict__ hbase,
                            const int* __restrict__ batch) {
    unsigned idx = blockIdx.x * 256u + threadIdx.x;
    unsigned wn = idx >> 5;
    unsigned c = (idx & 31u) << 2;
    if (wn >= 2 * NN) return;
    int ens = wn >= NN;
    unsigned n = wn - (unsigned)ens * NN;
    int g = batch[(size_t)ens * NN + n];
    const float* h = hbase + (size_t)ens * NN * HH;
    float4 v = *(const float4*)(h + (size_t)n * HH + c);
    atomicAdd((float4*)(&g_pool[ens][g * HH + c]), v);
    if (c == 0) atomicAdd(&g_cnt[ens][g], 1.0f);
}

__global__ void head_kernel(const float* __restrict__ W1all,
                            const float* __restrict__ b1all,
                            const float* __restrict__ W2all,
                            const float* __restrict__ b2all,
                            float* __restrict__ out) {
    int g = blockIdx.x;
    int ens = blockIdx.y;
    int c = threadIdx.x;  // 128 threads
    const float* W1 = W1all + (size_t)ens * 16384;
    const float* b1 = b1all + ens * 128;
    const float* W2 = W2all + (size_t)ens * 1280;
    const float* b2 = b2all + ens * 10;
    __shared__ float p[128];
    __shared__ float z[128];
    float cn = fmaxf(g_cnt[ens][g], 1.0f);
    p[c] = g_pool[ens][g * HH + c] / cn;
    __syncthreads();
    float acc = b1[c];
#pragma unroll 4
    for (int k = 0; k < 128; k++) acc += p[k] * W1[k * 128 + c];
    z[c] = fmaxf(acc, 0.f);
    __syncthreads();
    if (c < CC) {
        float y = b2[c];
#pragma unroll 4
        for (int k = 0; k < 128; k++) y += z[k] * W2[k * CC + c];
        out[((size_t)ens * GG + g) * CC + c] = y;
    }
}

// ---------------- driver ----------------
extern "C" void kernel_launch(void* const* d_in, const int* in_sizes, int n_in,
                              void* d_out, int out_size) {
    const float* x     = (const float*)d_in[0];
    const int*   ei    = (const int*)d_in[1];
    const int*   batch = (const int*)d_in[2];
    const float* c1W1  = (const float*)d_in[3];
    const float* c1b1  = (const float*)d_in[4];
    const float* c1W2  = (const float*)d_in[5];
    const float* c1b2  = (const float*)d_in[6];
    const float* c1g   = (const float*)d_in[7];
    const float* c1be  = (const float*)d_in[8];
    const float* c1m   = (const float*)d_in[9];
    const float* c1v   = (const float*)d_in[10];
    const float* c1e   = (const float*)d_in[11];
    const float* csW1  = (const float*)d_in[12];
    const float* csb1  = (const float*)d_in[13];
    const float* csW2  = (const float*)d_in[14];
    const float* csb2  = (const float*)d_in[15];
    const float* csg   = (const float*)d_in[16];
    const float* csbe  = (const float*)d_in[17];
    const float* csm   = (const float*)d_in[18];
    const float* csv   = (const float*)d_in[19];
    const float* cse   = (const float*)d_in[20];
    const float* l1W   = (const float*)d_in[21];
    const float* l1b   = (const float*)d_in[22];
    const float* l2W   = (const float*)d_in[23];
    const float* l2b   = (const float*)d_in[24];
    float* out = (float*)d_out;

    float* hF;
    __half *agg16, *x16, *h16A, *h16B;
    cudaGetSymbolAddress((void**)&agg16, g_agg16);
    cudaGetSymbolAddress((void**)&hF, g_hF);
    cudaGetSymbolAddress((void**)&x16, g_x16);
    cudaGetSymbolAddress((void**)&h16A, g_h16A);
    cudaGetSymbolAddress((void**)&h16B, g_h16B);

    const int SMEM_BYTES = MLP_SMEM_U32 * 4;  // 106,496 B (occ 2)
    cudaFuncSetAttribute(mlp_kernel, cudaFuncAttributeMaxDynamicSharedMemorySize,
                         SMEM_BYTES);

    const int IP_GRID   = 10 + ZB + XB;
    const int E_GRID    = (2 * (EE / 4) + 255) / 256;
    const int AGG_GRID  = (NN * 32 + 255) / 256;      // 2 nodes/warp
    const dim3 MLP_GRID((NN + 127) / 128, 2);
    const int POOL_GRID = (2 * NN * 32 + 255) / 256;

    // 1: init+prep+x16, 2: fill, 3: agg, 4: mlp (profiled slot)
    init_prep_kernel<<<IP_GRID, 256>>>(c1W1, c1W2, csW1, csW2, x);
    fill_kernel<<<E_GRID, 256>>>(ei);

    // layer 0 (conv1, per-ensemble weights: slots 0+ens / 2+ens) -> fp16 out
    agg_kernel<<<AGG_GRID, 256>>>(x16, agg16, c1e, 1);
    mlp_kernel<<<MLP_GRID, 256, SMEM_BYTES>>>(
        agg16, nullptr, h16A, 0, 1, 2, 1, c1b1, c1b2, c1g, c1be, c1m, c1v, 128);

    // layers 1..2 (shared weights: slots 4+l / 7+l) -> fp16 out
    const __half* cur = h16A;
    __half* nxt = h16B;
    for (int l = 0; l < 2; l++) {
        agg_kernel<<<AGG_GRID, 256>>>(cur, agg16, cse + l, 0);
        mlp_kernel<<<MLP_GRID, 256, SMEM_BYTES>>>(
            agg16, nullptr, nxt, 4 + l, 0, 7 + l, 0,
            csb1 + l * 128, csb2 + l * 128,
            csg + l * 128, csbe + l * 128, csm + l * 128, csv + l * 128, 0);
        const __half* tswap = cur;
        cur = nxt;
        nxt = (__half*)tswap;
    }

    // layer 3: fp32 out for pool
    agg_kernel<<<AGG_GRID, 256>>>(cur, agg16, cse + 2, 0);
    mlp_kernel<<<MLP_GRID, 256, SMEM_BYTES>>>(
        agg16, hF, nullptr, 6, 0, 9, 0,
        csb1 + 2 * 128, csb2 + 2 * 128,
        csg + 2 * 128, csbe + 2 * 128, csm + 2 * 128, csv + 2 * 128, 0);

    pool_kernel<<<POOL_GRID, 256>>>(hF, batch);
    head_kernel<<<dim3(GG, 2), 128>>>(l1W, l1b, l2W, l2b, out);
}

// round 16
// speedup vs baseline: 1.3849x; 1.1420x over previous
#include <cuda_runtime.h>
#include <cuda_bf16.h>
#include <cuda_fp16.h>
#include <math.h>
#include <stdint.h>

#define NN 50000
#define EE 800000
#define GG 128
#define HH 128
#define CC 10
#define BCAP 64   // per-node neighbor bucket capacity (max degree ~35)

// ---------------- scratch (__device__ globals; no allocs allowed) ------------
__device__ __half g_agg16[2][NN * HH];       // fp16 MLP input (agg output)
__device__ float g_hF[2][NN * HH];           // fp32 final-layer output (pool)
__device__ __half g_x16[2][NN * HH];         // fp16 copy of x for gather
__device__ __half g_h16A[2][NN * HH];        // fp16 inter-layer activations
__device__ __half g_h16B[2][NN * HH];
__device__ float g_pool[2][GG * HH];
__device__ float g_cnt[2][GG];
__device__ int g_bcnt[2][NN];
__device__ int g_bsrc[2][NN * BCAP];
// fp16 weights W^T: [matrix][128n * 68u32]
// slots: 0,1 = c1W1 ens0/1 ; 2,3 = c1W2 ens0/1 ; 4..6 = csW1 l ; 7..9 = csW2 l
__device__ uint32_t g_wsplit[10][8704];

// fp16 MMA, fp32 accumulate
#define MMAF16(c, a0, a1, a2, a3, b0, b1)                                    \
    asm volatile(                                                            \
        "mma.sync.aligned.m16n8k16.row.col.f32.f16.f16.f32 "                 \
        "{%0,%1,%2,%3}, {%4,%5,%6,%7}, {%8,%9}, {%0,%1,%2,%3};"              \
        : "+f"(c[0]), "+f"(c[1]), "+f"(c[2]), "+f"(c[3])                     \
        : "r"(a0), "r"(a1), "r"(a2), "r"(a3), "r"(b0), "r"(b1))

// u32-as-half2 add
__device__ __forceinline__ uint32_t h2add(uint32_t a, uint32_t b) {
    __half2 r = __hadd2(*(__half2*)&a, *(__half2*)&b);
    return *(uint32_t*)&r;
}

// ------- merged init: weight convert + zero counters + x->fp16 -------------
// blocks [0,10): weight convert; [10, 10+ZB): zeroing; [10+ZB, ...): x16
#define ZB ((2 * NN + 255) / 256)
#define XB ((2 * NN * HH) / (8 * 256))
__global__ void init_prep_kernel(const float* __restrict__ c1W1,
                                 const float* __restrict__ c1W2,
                                 const float* __restrict__ csW1,
                                 const float* __restrict__ csW2,
                                 const float* __restrict__ x) {
    if (blockIdx.x < 10) {
        int b = blockIdx.x;
        const float* W;
        if (b < 2)       W = c1W1 + (size_t)b * 16384;
        else if (b < 4)  W = c1W2 + (size_t)(b - 2) * 16384;
        else if (b < 7)  W = csW1 + (size_t)(b - 4) * 16384;
        else             W = csW2 + (size_t)(b - 7) * 16384;
        __half* whb = (__half*)g_wsplit[b];
        const float4* Wv = (const float4*)W;
        for (int idx = threadIdx.x; idx < 4096; idx += 256) {
            int k = idx >> 5, nq = idx & 31;
            float4 v = Wv[k * 32 + nq];
            float vv[4] = {v.x, v.y, v.z, v.w};
#pragma unroll
            for (int i = 0; i < 4; i++) {
                int n = 4 * nq + i;
                whb[n * 136 + k] = __float2half_rn(vv[i]);  // W^T [n][k]
            }
        }
    } else if (blockIdx.x < 10 + ZB) {
        int i = (blockIdx.x - 10) * 256 + threadIdx.x;
        if (i < 2 * NN) g_bcnt[0][i] = 0;          // contiguous [2][NN]
        if (i < 2 * GG * HH) g_pool[0][i] = 0.f;
        if (i < 2 * GG) g_cnt[0][i] = 0.f;
    } else {
        size_t i = ((size_t)(blockIdx.x - 10 - ZB) * 256 + threadIdx.x) * 8;
        float4 a = *(const float4*)(x + i);
        float4 b = *(const float4*)(x + i + 4);
        __half2 h0 = __floats2half2_rn(a.x, a.y);
        __half2 h1 = __floats2half2_rn(a.z, a.w);
        __half2 h2 = __floats2half2_rn(b.x, b.y);
        __half2 h3 = __floats2half2_rn(b.z, b.w);
        uint4 o;
        o.x = *(uint32_t*)&h0; o.y = *(uint32_t*)&h1;
        o.z = *(uint32_t*)&h2; o.w = *(uint32_t*)&h3;
        *(uint4*)((__half*)g_x16 + i) = o;
    }
}

// ---------------- bucket fill: 4 edges/thread via int4 ----------------
__global__ void fill_kernel(const int* __restrict__ ei) {
    int q = blockIdx.x * 256 + threadIdx.x;      // quad index over 2*EE/4
    if (q >= 2 * (EE / 4)) return;
    int ens = q >= (EE / 4);
    int e4 = q - ens * (EE / 4);
    const int* base = ei + (size_t)ens * 2 * EE;
    int4 s4 = __ldg((const int4*)(base) + e4);
    int4 d4 = __ldg((const int4*)(base + EE) + e4);
    int* bc = g_bcnt[ens];
    int* bs = g_bsrc[ens];
    int slot;
    slot = atomicAdd(&bc[d4.x], 1); bs[(size_t)d4.x * BCAP + slot] = s4.x;
    slot = atomicAdd(&bc[d4.y], 1); bs[(size_t)d4.y * BCAP + slot] = s4.y;
    slot = atomicAdd(&bc[d4.z], 1); bs[(size_t)d4.z * BCAP + slot] = s4.z;
    slot = atomicAdd(&bc[d4.w], 1); bs[(size_t)d4.w * BCAP + slot] = s4.w;
}

// 2 nodes per warp: half-warp per node, uint4 (16B) per lane.
__global__ __launch_bounds__(256, 6) void agg_kernel(
    const __half* __restrict__ xbase,
    __half* __restrict__ aggbase,
    const float* __restrict__ eps_p, int eps_stride) {
    unsigned idx = blockIdx.x * 256u + threadIdx.x;
    unsigned w = idx >> 5;
    unsigned lane = idx & 31u;
    unsigned g = 2u * w + (lane >> 4);   // global node id
    unsigned s = lane & 15u;             // 16B chunk (uint4) within 256B row
    if (g >= 2 * NN) return;
    int ens = g >= NN;
    unsigned n = g - (unsigned)ens * NN;
    float e1 = 1.0f + eps_p[ens * eps_stride];
    const uint4* xv = (const uint4*)(xbase + (size_t)ens * NN * HH);  // 16/row
    const int* __restrict__ bucket = &g_bsrc[ens][(size_t)n * BCAP];
    const int4* __restrict__ b4 = (const int4*)bucket;  // 256B-aligned rows
    int deg = g_bcnt[ens][n];

    uint32_t A0 = 0, A1 = 0, A2 = 0, A3 = 0;   // chain A (4 half2)
    uint32_t B0 = 0, B1 = 0, B2 = 0, B3 = 0;   // chain B

    uint4 self = __ldg(&xv[(size_t)n * 16 + s]);

    int e = 0;
    for (; e + 4 <= deg; e += 4) {
        int4 ia = __ldg(&b4[e >> 2]);
        uint4 p0 = __ldg(&xv[(size_t)(unsigned)ia.x * 16 + s]);
        uint4 p1 = __ldg(&xv[(size_t)(unsigned)ia.y * 16 + s]);
        uint4 p2 = __ldg(&xv[(size_t)(unsigned)ia.z * 16 + s]);
        uint4 p3 = __ldg(&xv[(size_t)(unsigned)ia.w * 16 + s]);
        A0 = h2add(A0, p0.x); A1 = h2add(A1, p0.y);
        A2 = h2add(A2, p0.z); A3 = h2add(A3, p0.w);
        B0 = h2add(B0, p1.x); B1 = h2add(B1, p1.y);
        B2 = h2add(B2, p1.z); B3 = h2add(B3, p1.w);
        A0 = h2add(A0, p2.x); A1 = h2add(A1, p2.y);
        A2 = h2add(A2, p2.z); A3 = h2add(A3, p2.w);
        B0 = h2add(B0, p3.x); B1 = h2add(B1, p3.y);
        B2 = h2add(B2, p3.z); B3 = h2add(B3, p3.w);
    }
    for (; e < deg; e++) {
        int sn = __ldg(&bucket[e]);
        uint4 p = __ldg(&xv[(size_t)(unsigned)sn * 16 + s]);
        if (e & 1) {
            B0 = h2add(B0, p.x); B1 = h2add(B1, p.y);
            B2 = h2add(B2, p.z); B3 = h2add(B3, p.w);
        } else {
            A0 = h2add(A0, p.x); A1 = h2add(A1, p.y);
            A2 = h2add(A2, p.z); A3 = h2add(A3, p.w);
        }
    }

    // combine 2 chains + (1+eps)*self in fp32, per 32-bit word
    uint4 o;
    uint32_t ca[4] = {A0, A1, A2, A3};
    uint32_t cb[4] = {B0, B1, B2, B3};
    uint32_t sv[4] = {self.x, self.y, self.z, self.w};
    uint32_t ov[4];
#pragma unroll
    for (int k = 0; k < 4; k++) {
        float2 fa = __half22float2(*(__half2*)&ca[k]);
        float2 fb = __half22float2(*(__half2*)&cb[k]);
        float2 fs = __half22float2(*(__half2*)&sv[k]);
        float rx = fa.x + fb.x + e1 * fs.x;
        float ry = fa.y + fb.y + e1 * fs.y;
        __half2 r = __floats2half2_rn(rx, ry);
        ov[k] = *(uint32_t*)&r;
    }
    o.x = ov[0]; o.y = ov[1]; o.z = ov[2]; o.w = ov[3];
    ((uint4*)(aggbase + (size_t)ens * NN * HH))[(size_t)n * 16 + s] = o;
}

// ---------------- MLP: fp16 A x fp16 W, mma.sync, occ 3 ---------------------
// smem u32: As[8704] WH[8704] prm[512] = 17920 u32 (71.7KB) -> 3 CTAs/SM
#define MLP_SMEM_U32 17920

__device__ __forceinline__ void copy_w(const uint32_t* __restrict__ gh,
                                       uint32_t* wh, int tid) {
    const uint4* gh4 = (const uint4*)gh;
    uint4* wh4 = (uint4*)wh;
    for (int i = tid; i < 2176; i += 256) {
        wh4[i] = gh4[i];
    }
}

// 32x64 warp tile: rows r0+16*rs (+8), cols nbase + 8j + ...
__device__ __forceinline__ void do_gemm(const uint32_t* __restrict__ As,
                                        const uint32_t* __restrict__ WH,
                                        int r0, int nbase, int tg, int tp,
                                        float acc[2][8][4]) {
#pragma unroll
    for (int c = 0; c < 8; c++) {
        int ko = tp + 8 * c;
        uint32_t ah[2][4];
#pragma unroll
        for (int rs = 0; rs < 2; rs++) {
            int ar = (r0 + 16 * rs) * 68;
            int ar8 = ar + 8 * 68;
            ah[rs][0] = As[ar + ko];      ah[rs][1] = As[ar8 + ko];
            ah[rs][2] = As[ar + ko + 4];  ah[rs][3] = As[ar8 + ko + 4];
        }
#pragma unroll
        for (int j = 0; j < 8; j++) {
            int nb = (nbase + 8 * j + tg) * 68 + ko;
            uint32_t bh0 = WH[nb], bh1 = WH[nb + 4];
#pragma unroll
            for (int rs = 0; rs < 2; rs++) {
                MMAF16(acc[rs][j], ah[rs][0], ah[rs][1], ah[rs][2], ah[rs][3], bh0, bh1);
            }
        }
    }
}

__global__ __launch_bounds__(256, 3) void mlp_kernel(
    const __half* __restrict__ Abase, float* __restrict__ outbase,
    __half* __restrict__ out16base,
    int w1slot, int w1stride, int w2slot, int w2stride,
    const float* __restrict__ b1, const float* __restrict__ b2,
    const float* __restrict__ gamma, const float* __restrict__ beta,
    const float* __restrict__ mean, const float* __restrict__ var, int vs) {
    extern __shared__ uint32_t sm32[];
    uint32_t* As = sm32;
    uint32_t* WH = sm32 + 8704;
    float* b1s = (float*)(sm32 + 17408);
    float* b2s = b1s + 128;
    float* scs = b2s + 128;
    float* shs = scs + 128;

    int ens = blockIdx.y;
    const __half* A = Abase + (size_t)ens * NN * HH;
    b1 += ens * vs;  b2 += ens * vs;
    gamma += ens * vs;  beta += ens * vs;  mean += ens * vs;  var += ens * vs;
    int s1 = w1slot + ens * w1stride;
    int s2 = w2slot + ens * w2stride;

    int tid = threadIdx.x;
    int wid = tid >> 5, t = tid & 31, tg = t >> 2, tp = t & 3;
    int wm = wid & 3, wcol = wid >> 2;
    int rb = blockIdx.x * 128;

    if (tid < 128) {
        b1s[tid] = b1[tid];
        b2s[tid] = b2[tid];
        float sc = gamma[tid] * rsqrtf(var[tid] + 1e-5f);
        scs[tid] = sc;
        shs[tid] = beta[tid] - mean[tid] * sc;
    }

    // stage A tile (128 rows x 128 halves), pure copy
    {
        const uint2* Av = (const uint2*)A;  // 32 uint2 per row
        uint2* As2 = (uint2*)As;            // stride 34 uint2
        for (int idx = tid; idx < 4096; idx += 256) {
            int r = idx >> 5, q = idx & 31;
            int gr = rb + r;
            uint2 v = (gr < NN) ? Av[(size_t)gr * 32 + q] : make_uint2(0u, 0u);
            As2[r * 34 + q] = v;
        }
    }
    copy_w(g_wsplit[s1], WH, tid);
    __syncthreads();

    float acc[2][8][4];
#pragma unroll
    for (int rs = 0; rs < 2; rs++)
#pragma unroll
        for (int j = 0; j < 8; j++)
#pragma unroll
            for (int q = 0; q < 4; q++) acc[rs][j][q] = 0.f;

    int r0 = wm * 32 + tg;
    int nbase = wcol * 64;

    do_gemm(As, WH, r0, nbase, tg, tp, acc);
    __syncthreads();

    // W1 dead; start W2 copy first so its L2 latency overlaps epilogue math
    copy_w(g_wsplit[s2], WH, tid);

    // epilogue 1: h1 = relu(acc + b1) -> fp16 back into As (own rows/cols)
#pragma unroll
    for (int rs = 0; rs < 2; rs++) {
        int arow = (r0 + 16 * rs) * 68;
        int arow8 = arow + 8 * 68;
#pragma unroll
        for (int j = 0; j < 8; j++) {
            int col0 = nbase + 8 * j + 2 * tp;
            int cu = col0 >> 1;
            float bb0 = b1s[col0], bb1 = b1s[col0 + 1];
            float v0 = fmaxf(acc[rs][j][0] + bb0, 0.f);
            float v1 = fmaxf(acc[rs][j][1] + bb1, 0.f);
            float v2 = fmaxf(acc[rs][j][2] + bb0, 0.f);
            float v3 = fmaxf(acc[rs][j][3] + bb1, 0.f);
            __half2 p0 = __floats2half2_rn(v0, v1);
            __half2 p1 = __floats2half2_rn(v2, v3);
            As[arow + cu] = *(uint32_t*)&p0;
            As[arow8 + cu] = *(uint32_t*)&p1;
            acc[rs][j][0] = acc[rs][j][1] = acc[rs][j][2] = acc[rs][j][3] = 0.f;
        }
    }
    __syncthreads();

    do_gemm(As, WH, r0, nbase, tg, tp, acc);

    // final epilogue: relu -> BN -> relu -> global (fp16 or fp32)
#pragma unroll
    for (int rs = 0; rs < 2; rs++) {
        int gr0 = rb + r0 + 16 * rs;
        int gr8 = gr0 + 8;
#pragma unroll
        for (int j = 0; j < 8; j++) {
            int col0 = nbase + 8 * j + 2 * tp;
            float bb0 = b2s[col0], bb1 = b2s[col0 + 1];
            float s0 = scs[col0], s1f = scs[col0 + 1];
            float t0 = shs[col0], t1 = shs[col0 + 1];
            float v0 = fmaxf(acc[rs][j][0] + bb0, 0.f);
            float v1 = fmaxf(acc[rs][j][1] + bb1, 0.f);
            float v2 = fmaxf(acc[rs][j][2] + bb0, 0.f);
            float v3 = fmaxf(acc[rs][j][3] + bb1, 0.f);
            float o0 = fmaxf(v0 * s0 + t0, 0.f);
            float o1 = fmaxf(v1 * s1f + t1, 0.f);
            float o2 = fmaxf(v2 * s0 + t0, 0.f);
            float o3 = fmaxf(v3 * s1f + t1, 0.f);
            if (out16base) {
                __half* o16 = out16base + (size_t)ens * NN * HH;
                if (gr0 < NN)
                    *(__half2*)(o16 + (size_t)gr0 * HH + col0) = __floats2half2_rn(o0, o1);
                if (gr8 < NN)
                    *(__half2*)(o16 + (size_t)gr8 * HH + col0) = __floats2half2_rn(o2, o3);
            } else {
                float* out = outbase + (size_t)ens * NN * HH;
                if (gr0 < NN)
                    *(float2*)(out + (size_t)gr0 * HH + col0) = make_float2(o0, o1);
                if (gr8 < NN)
                    *(float2*)(out + (size_t)gr8 * HH + col0) = make_float2(o2, o3);
            }
        }
    }
}

// ---------------- pool + head ----------------
__global__ void pool_kernel(const float* __restrict__ hbase,
                            const int* __restrict__ batch) {
    unsigned idx = blockIdx.x * 256u + threadIdx.x;
    unsigned wn = idx >> 5;
    unsigned c = (idx & 31u) << 2;
    if (wn >= 2 * NN) return;
    int ens = wn >= NN;
    unsigned n = wn - (unsigned)ens * NN;
    int g = batch[(size_t)ens * NN + n];
    const float* h = hbase + (size_t)ens * NN * HH;
    float4 v = *(const float4*)(h + (size_t)n * HH + c);
    atomicAdd((float4*)(&g_pool[ens][g * HH + c]), v);
    if (c == 0) atomicAdd(&g_cnt[ens][g], 1.0f);
}

__global__ void head_kernel(const float* __restrict__ W1all,
                            const float* __restrict__ b1all,
                            const float* __restrict__ W2all,
                            const float* __restrict__ b2all,
                            float* __restrict__ out) {
    int g = blockIdx.x;
    int ens = blockIdx.y;
    int c = threadIdx.x;  // 128 threads
    const float* W1 = W1all + (size_t)ens * 16384;
    const float* b1 = b1all + ens * 128;
    const float* W2 = W2all + (size_t)ens * 1280;
    const float* b2 = b2all + ens * 10;
    __shared__ float p[128];
    __shared__ float z[128];
    float cn = fmaxf(g_cnt[ens][g], 1.0f);
    p[c] = g_pool[ens][g * HH + c] / cn;
    __syncthreads();
    float acc = b1[c];
#pragma unroll 4
    for (int k = 0; k < 128; k++) acc += p[k] * W1[k * 128 + c];
    z[c] = fmaxf(acc, 0.f);
    __syncthreads();
    if (c < CC) {
        float y = b2[c];
#pragma unroll 4
        for (int k = 0; k < 128; k++) y += z[k] * W2[k * CC + c];
        out[((size_t)ens * GG + g) * CC + c] = y;
    }
}

// ---------------- driver ----------------
extern "C" void kernel_launch(void* const* d_in, const int* in_sizes, int n_in,
                              void* d_out, int out_size) {
    const float* x     = (const float*)d_in[0];
    const int*   ei    = (const int*)d_in[1];
    const int*   batch = (const int*)d_in[2];
    const float* c1W1  = (const float*)d_in[3];
    const float* c1b1  = (const float*)d_in[4];
    const float* c1W2  = (const float*)d_in[5];
    const float* c1b2  = (const float*)d_in[6];
    const float* c1g   = (const float*)d_in[7];
    const float* c1be  = (const float*)d_in[8];
    const float* c1m   = (const float*)d_in[9];
    const float* c1v   = (const float*)d_in[10];
    const float* c1e   = (const float*)d_in[11];
    const float* csW1  = (const float*)d_in[12];
    const float* csb1  = (const float*)d_in[13];
    const float* csW2  = (const float*)d_in[14];
    const float* csb2  = (const float*)d_in[15];
    const float* csg   = (const float*)d_in[16];
    const float* csbe  = (const float*)d_in[17];
    const float* csm   = (const float*)d_in[18];
    const float* csv   = (const float*)d_in[19];
    const float* cse   = (const float*)d_in[20];
    const float* l1W   = (const float*)d_in[21];
    const float* l1b   = (const float*)d_in[22];
    const float* l2W   = (const float*)d_in[23];
    const float* l2b   = (const float*)d_in[24];
    float* out = (float*)d_out;

    float* hF;
    __half *agg16, *x16, *h16A, *h16B;
    cudaGetSymbolAddress((void**)&agg16, g_agg16);
    cudaGetSymbolAddress((void**)&hF, g_hF);
    cudaGetSymbolAddress((void**)&x16, g_x16);
    cudaGetSymbolAddress((void**)&h16A, g_h16A);
    cudaGetSymbolAddress((void**)&h16B, g_h16B);

    const int SMEM_BYTES = MLP_SMEM_U32 * 4;  // 71,680 B (occ 3)
    cudaFuncSetAttribute(mlp_kernel, cudaFuncAttributeMaxDynamicSharedMemorySize,
                         SMEM_BYTES);

    const int IP_GRID   = 10 + ZB + XB;
    const int E_GRID    = (2 * (EE / 4) + 255) / 256;
    const int AGG_GRID  = (NN * 32 + 255) / 256;      // 2 nodes/warp
    const dim3 MLP_GRID((NN + 127) / 128, 2);
    const int POOL_GRID = (2 * NN * 32 + 255) / 256;

    // 1: init+prep+x16, 2: fill, 3: agg, 4: mlp (profiled slot)
    init_prep_kernel<<<IP_GRID, 256>>>(c1W1, c1W2, csW1, csW2, x);
    fill_kernel<<<E_GRID, 256>>>(ei);

    // layer 0 (conv1, per-ensemble weights: slots 0+ens / 2+ens) -> fp16 out
    agg_kernel<<<AGG_GRID, 256>>>(x16, agg16, c1e, 1);
    mlp_kernel<<<MLP_GRID, 256, SMEM_BYTES>>>(
        agg16, nullptr, h16A, 0, 1, 2, 1, c1b1, c1b2, c1g, c1be, c1m, c1v, 128);

    // layers 1..2 (shared weights: slots 4+l / 7+l) -> fp16 out
    const __half* cur = h16A;
    __half* nxt = h16B;
    for (int l = 0; l < 2; l++) {
        agg_kernel<<<AGG_GRID, 256>>>(cur, agg16, cse + l, 0);
        mlp_kernel<<<MLP_GRID, 256, SMEM_BYTES>>>(
            agg16, nullptr, nxt, 4 + l, 0, 7 + l, 0,
            csb1 + l * 128, csb2 + l * 128,
            csg + l * 128, csbe + l * 128, csm + l * 128, csv + l * 128, 0);
        const __half* tswap = cur;
        cur = nxt;
        nxt = (__half*)tswap;
    }

    // layer 3: fp32 out for pool
    agg_kernel<<<AGG_GRID, 256>>>(cur, agg16, cse + 2, 0);
    mlp_kernel<<<MLP_GRID, 256, SMEM_BYTES>>>(
        agg16, hF, nullptr, 6, 0, 9, 0,
        csb1 + 2 * 128, csb2 + 2 * 128,
        csg + 2 * 128, csbe + 2 * 128, csm + 2 * 128, csv + 2 * 128, 0);

    pool_kernel<<<POOL_GRID, 256>>>(hF, batch);
    head_kernel<<<dim3(GG, 2), 128>>>(l1W, l1b, l2W, l2b, out);
}

// round 17
// speedup vs baseline: 1.4113x; 1.0190x over previous
#include <cuda_runtime.h>
#include <cuda_bf16.h>
#include <cuda_fp16.h>
#include <math.h>
#include <stdint.h>

#define NN 50000
#define EE 800000
#define GG 128
#define HH 128
#define CC 10
#define BCAP 64   // per-node neighbor bucket capacity (max degree ~35)

// ---------------- scratch (__device__ globals; no allocs allowed) ------------
__device__ __half g_agg16[2][NN * HH];       // fp16 MLP input (agg output)
__device__ float g_hF[2][NN * HH];           // fp32 final-layer output (pool)
__device__ __half g_x16[2][NN * HH];         // fp16 copy of x for gather
__device__ __half g_h16A[2][NN * HH];        // fp16 inter-layer activations
__device__ __half g_h16B[2][NN * HH];
__device__ float g_pool[2][GG * HH];
__device__ float g_cnt[2][GG];
__device__ int g_bcnt[2][NN];
__device__ int g_bsrc[2][NN * BCAP];
// fp16 weights W^T: [matrix][128n * 68u32]
// slots: 0,1 = c1W1 ens0/1 ; 2,3 = c1W2 ens0/1 ; 4..6 = csW1 l ; 7..9 = csW2 l
__device__ uint32_t g_wsplit[10][8704];

// fp16 MMA, fp32 accumulate
#define MMAF16(c, a0, a1, a2, a3, b0, b1)                                    \
    asm volatile(                                                            \
        "mma.sync.aligned.m16n8k16.row.col.f32.f16.f16.f32 "                 \
        "{%0,%1,%2,%3}, {%4,%5,%6,%7}, {%8,%9}, {%0,%1,%2,%3};"              \
        : "+f"(c[0]), "+f"(c[1]), "+f"(c[2]), "+f"(c[3])                     \
        : "r"(a0), "r"(a1), "r"(a2), "r"(a3), "r"(b0), "r"(b1))

// u32-as-half2 add
__device__ __forceinline__ uint32_t h2add(uint32_t a, uint32_t b) {
    __half2 r = __hadd2(*(__half2*)&a, *(__half2*)&b);
    return *(uint32_t*)&r;
}

// ------- merged init: weight convert + zero counters + x->fp16 -------------
#define ZB ((2 * NN + 255) / 256)
#define XB ((2 * NN * HH) / (8 * 256))
__global__ void init_prep_kernel(const float* __restrict__ c1W1,
                                 const float* __restrict__ c1W2,
                                 const float* __restrict__ csW1,
                                 const float* __restrict__ csW2,
                                 const float* __restrict__ x) {
    if (blockIdx.x < 10) {
        int b = blockIdx.x;
        const float* W;
        if (b < 2)       W = c1W1 + (size_t)b * 16384;
        else if (b < 4)  W = c1W2 + (size_t)(b - 2) * 16384;
        else if (b < 7)  W = csW1 + (size_t)(b - 4) * 16384;
        else             W = csW2 + (size_t)(b - 7) * 16384;
        __half* whb = (__half*)g_wsplit[b];
        const float4* Wv = (const float4*)W;
        for (int idx = threadIdx.x; idx < 4096; idx += 256) {
            int k = idx >> 5, nq = idx & 31;
            float4 v = Wv[k * 32 + nq];
            float vv[4] = {v.x, v.y, v.z, v.w};
#pragma unroll
            for (int i = 0; i < 4; i++) {
                int n = 4 * nq + i;
                whb[n * 136 + k] = __float2half_rn(vv[i]);  // W^T [n][k]
            }
        }
    } else if (blockIdx.x < 10 + ZB) {
        int i = (blockIdx.x - 10) * 256 + threadIdx.x;
        if (i < 2 * NN) g_bcnt[0][i] = 0;          // contiguous [2][NN]
        if (i < 2 * GG * HH) g_pool[0][i] = 0.f;
        if (i < 2 * GG) g_cnt[0][i] = 0.f;
    } else {
        size_t i = ((size_t)(blockIdx.x - 10 - ZB) * 256 + threadIdx.x) * 8;
        float4 a = *(const float4*)(x + i);
        float4 b = *(const float4*)(x + i + 4);
        __half2 h0 = __floats2half2_rn(a.x, a.y);
        __half2 h1 = __floats2half2_rn(a.z, a.w);
        __half2 h2 = __floats2half2_rn(b.x, b.y);
        __half2 h3 = __floats2half2_rn(b.z, b.w);
        uint4 o;
        o.x = *(uint32_t*)&h0; o.y = *(uint32_t*)&h1;
        o.z = *(uint32_t*)&h2; o.w = *(uint32_t*)&h3;
        *(uint4*)((__half*)g_x16 + i) = o;
    }
}

// ---------------- bucket fill: 4 edges/thread via int4 ----------------
__global__ void fill_kernel(const int* __restrict__ ei) {
    int q = blockIdx.x * 256 + threadIdx.x;      // quad index over 2*EE/4
    if (q >= 2 * (EE / 4)) return;
    int ens = q >= (EE / 4);
    int e4 = q - ens * (EE / 4);
    const int* base = ei + (size_t)ens * 2 * EE;
    int4 s4 = __ldg((const int4*)(base) + e4);
    int4 d4 = __ldg((const int4*)(base + EE) + e4);
    int* bc = g_bcnt[ens];
    int* bs = g_bsrc[ens];
    int slot;
    slot = atomicAdd(&bc[d4.x], 1); bs[(size_t)d4.x * BCAP + slot] = s4.x;
    slot = atomicAdd(&bc[d4.y], 1); bs[(size_t)d4.y * BCAP + slot] = s4.y;
    slot = atomicAdd(&bc[d4.z], 1); bs[(size_t)d4.z * BCAP + slot] = s4.z;
    slot = atomicAdd(&bc[d4.w], 1); bs[(size_t)d4.w * BCAP + slot] = s4.w;
}

// 2 nodes per warp: half-warp per node, uint4 (16B) per lane.
__global__ __launch_bounds__(256, 6) void agg_kernel(
    const __half* __restrict__ xbase,
    __half* __restrict__ aggbase,
    const float* __restrict__ eps_p, int eps_stride) {
    unsigned idx = blockIdx.x * 256u + threadIdx.x;
    unsigned w = idx >> 5;
    unsigned lane = idx & 31u;
    unsigned g = 2u * w + (lane >> 4);   // global node id
    unsigned s = lane & 15u;             // 16B chunk (uint4) within 256B row
    if (g >= 2 * NN) return;
    int ens = g >= NN;
    unsigned n = g - (unsigned)ens * NN;
    float e1 = 1.0f + eps_p[ens * eps_stride];
    const uint4* xv = (const uint4*)(xbase + (size_t)ens * NN * HH);  // 16/row
    const int* __restrict__ bucket = &g_bsrc[ens][(size_t)n * BCAP];
    const int4* __restrict__ b4 = (const int4*)bucket;  // 256B-aligned rows
    int deg = g_bcnt[ens][n];

    uint32_t A0 = 0, A1 = 0, A2 = 0, A3 = 0;   // chain A (4 half2)
    uint32_t B0 = 0, B1 = 0, B2 = 0, B3 = 0;   // chain B

    uint4 self = __ldg(&xv[(size_t)n * 16 + s]);

    int e = 0;
    for (; e + 4 <= deg; e += 4) {
        int4 ia = __ldg(&b4[e >> 2]);
        uint4 p0 = __ldg(&xv[(size_t)(unsigned)ia.x * 16 + s]);
        uint4 p1 = __ldg(&xv[(size_t)(unsigned)ia.y * 16 + s]);
        uint4 p2 = __ldg(&xv[(size_t)(unsigned)ia.z * 16 + s]);
        uint4 p3 = __ldg(&xv[(size_t)(unsigned)ia.w * 16 + s]);
        A0 = h2add(A0, p0.x); A1 = h2add(A1, p0.y);
        A2 = h2add(A2, p0.z); A3 = h2add(A3, p0.w);
        B0 = h2add(B0, p1.x); B1 = h2add(B1, p1.y);
        B2 = h2add(B2, p1.z); B3 = h2add(B3, p1.w);
        A0 = h2add(A0, p2.x); A1 = h2add(A1, p2.y);
        A2 = h2add(A2, p2.z); A3 = h2add(A3, p2.w);
        B0 = h2add(B0, p3.x); B1 = h2add(B1, p3.y);
        B2 = h2add(B2, p3.z); B3 = h2add(B3, p3.w);
    }
    for (; e < deg; e++) {
        int sn = __ldg(&bucket[e]);
        uint4 p = __ldg(&xv[(size_t)(unsigned)sn * 16 + s]);
        if (e & 1) {
            B0 = h2add(B0, p.x); B1 = h2add(B1, p.y);
            B2 = h2add(B2, p.z); B3 = h2add(B3, p.w);
        } else {
            A0 = h2add(A0, p.x); A1 = h2add(A1, p.y);
            A2 = h2add(A2, p.z); A3 = h2add(A3, p.w);
        }
    }

    // combine 2 chains + (1+eps)*self in fp32, per 32-bit word
    uint4 o;
    uint32_t ca[4] = {A0, A1, A2, A3};
    uint32_t cb[4] = {B0, B1, B2, B3};
    uint32_t sv[4] = {self.x, self.y, self.z, self.w};
    uint32_t ov[4];
#pragma unroll
    for (int k = 0; k < 4; k++) {
        float2 fa = __half22float2(*(__half2*)&ca[k]);
        float2 fb = __half22float2(*(__half2*)&cb[k]);
        float2 fs = __half22float2(*(__half2*)&sv[k]);
        float rx = fa.x + fb.x + e1 * fs.x;
        float ry = fa.y + fb.y + e1 * fs.y;
        __half2 r = __floats2half2_rn(rx, ry);
        ov[k] = *(uint32_t*)&r;
    }
    o.x = ov[0]; o.y = ov[1]; o.z = ov[2]; o.w = ov[3];
    ((uint4*)(aggbase + (size_t)ens * NN * HH))[(size_t)n * 16 + s] = o;
}

// ---------------- MLP: fp16, 64-row tiles, occ 4 ----------------------------
// smem u32: As[4352] WH[8704] prm[512] = 13568 u32 (54.3KB) -> 4 CTAs/SM
#define MLP_SMEM_U32 13568

__device__ __forceinline__ void copy_w(const uint32_t* __restrict__ gh,
                                       uint32_t* wh, int tid) {
    const uint4* gh4 = (const uint4*)gh;
    uint4* wh4 = (uint4*)wh;
    for (int i = tid; i < 2176; i += 256) {
        wh4[i] = gh4[i];
    }
}

// 16x64 warp tile: rows r0..r0+15, cols nbase + 8j
__device__ __forceinline__ void do_gemm(const uint32_t* __restrict__ As,
                                        const uint32_t* __restrict__ WH,
                                        int r0, int nbase, int tg, int tp,
                                        float acc[8][4]) {
#pragma unroll
    for (int c = 0; c < 8; c++) {
        int ko = tp + 8 * c;
        int ar = r0 * 68;
        int ar8 = ar + 8 * 68;
        uint32_t a0 = As[ar + ko], a1 = As[ar8 + ko];
        uint32_t a2 = As[ar + ko + 4], a3 = As[ar8 + ko + 4];
#pragma unroll
        for (int j = 0; j < 8; j++) {
            int nb = (nbase + 8 * j + tg) * 68 + ko;
            uint32_t bh0 = WH[nb], bh1 = WH[nb + 4];
            MMAF16(acc[j], a0, a1, a2, a3, bh0, bh1);
        }
    }
}

__global__ __launch_bounds__(256, 4) void mlp_kernel(
    const __half* __restrict__ Abase, float* __restrict__ outbase,
    __half* __restrict__ out16base,
    int w1slot, int w1stride, int w2slot, int w2stride,
    const float* __restrict__ b1, const float* __restrict__ b2,
    const float* __restrict__ gamma, const float* __restrict__ beta,
    const float* __restrict__ mean, const float* __restrict__ var, int vs) {
    extern __shared__ uint32_t sm32[];
    uint32_t* As = sm32;
    uint32_t* WH = sm32 + 4352;
    float* b1s = (float*)(sm32 + 13056);
    float* b2s = b1s + 128;
    float* scs = b2s + 128;
    float* shs = scs + 128;

    int ens = blockIdx.y;
    const __half* A = Abase + (size_t)ens * NN * HH;
    b1 += ens * vs;  b2 += ens * vs;
    gamma += ens * vs;  beta += ens * vs;  mean += ens * vs;  var += ens * vs;
    int s1 = w1slot + ens * w1stride;
    int s2 = w2slot + ens * w2stride;

    int tid = threadIdx.x;
    int wid = tid >> 5, t = tid & 31, tg = t >> 2, tp = t & 3;
    int wm = wid & 3, wcol = wid >> 2;
    int rb = blockIdx.x * 64;

    if (tid < 128) {
        b1s[tid] = b1[tid];
        b2s[tid] = b2[tid];
        float sc = gamma[tid] * rsqrtf(var[tid] + 1e-5f);
        scs[tid] = sc;
        shs[tid] = beta[tid] - mean[tid] * sc;
    }

    // stage A tile (64 rows x 128 halves), pure copy
    {
        const uint2* Av = (const uint2*)A;  // 32 uint2 per row
        uint2* As2 = (uint2*)As;            // stride 34 uint2
        for (int idx = tid; idx < 2048; idx += 256) {
            int r = idx >> 5, q = idx & 31;
            int gr = rb + r;
            uint2 v = (gr < NN) ? Av[(size_t)gr * 32 + q] : make_uint2(0u, 0u);
            As2[r * 34 + q] = v;
        }
    }
    copy_w(g_wsplit[s1], WH, tid);
    __syncthreads();

    float acc[8][4];
#pragma unroll
    for (int j = 0; j < 8; j++)
#pragma unroll
        for (int q = 0; q < 4; q++) acc[j][q] = 0.f;

    int r0 = wm * 16 + tg;
    int nbase = wcol * 64;

    do_gemm(As, WH, r0, nbase, tg, tp, acc);
    __syncthreads();

    // W1 dead; start W2 copy first so its L2 latency overlaps epilogue math
    copy_w(g_wsplit[s2], WH, tid);

    // epilogue 1: h1 = relu(acc + b1) -> fp16 back into As (own rows/cols)
    {
        int arow = r0 * 68;
        int arow8 = arow + 8 * 68;
#pragma unroll
        for (int j = 0; j < 8; j++) {
            int col0 = nbase + 8 * j + 2 * tp;
            int cu = col0 >> 1;
            float bb0 = b1s[col0], bb1 = b1s[col0 + 1];
            float v0 = fmaxf(acc[j][0] + bb0, 0.f);
            float v1 = fmaxf(acc[j][1] + bb1, 0.f);
            float v2 = fmaxf(acc[j][2] + bb0, 0.f);
            float v3 = fmaxf(acc[j][3] + bb1, 0.f);
            __half2 p0 = __floats2half2_rn(v0, v1);
            __half2 p1 = __floats2half2_rn(v2, v3);
            As[arow + cu] = *(uint32_t*)&p0;
            As[arow8 + cu] = *(uint32_t*)&p1;
            acc[j][0] = acc[j][1] = acc[j][2] = acc[j][3] = 0.f;
        }
    }
    __syncthreads();

    do_gemm(As, WH, r0, nbase, tg, tp, acc);

    // final epilogue: relu -> BN -> relu -> global (fp16 or fp32)
    {
        int gr0 = rb + r0;
        int gr8 = gr0 + 8;
#pragma unroll
        for (int j = 0; j < 8; j++) {
            int col0 = nbase + 8 * j + 2 * tp;
            float bb0 = b2s[col0], bb1 = b2s[col0 + 1];
            float s0 = scs[col0], s1f = scs[col0 + 1];
            float t0 = shs[col0], t1 = shs[col0 + 1];
            float v0 = fmaxf(acc[j][0] + bb0, 0.f);
            float v1 = fmaxf(acc[j][1] + bb1, 0.f);
            float v2 = fmaxf(acc[j][2] + bb0, 0.f);
            float v3 = fmaxf(acc[j][3] + bb1, 0.f);
            float o0 = fmaxf(v0 * s0 + t0, 0.f);
            float o1 = fmaxf(v1 * s1f + t1, 0.f);
            float o2 = fmaxf(v2 * s0 + t0, 0.f);
            float o3 = fmaxf(v3 * s1f + t1, 0.f);
            if (out16base) {
                __half* o16 = out16base + (size_t)ens * NN * HH;
                if (gr0 < NN)
                    *(__half2*)(o16 + (size_t)gr0 * HH + col0) = __floats2half2_rn(o0, o1);
                if (gr8 < NN)
                    *(__half2*)(o16 + (size_t)gr8 * HH + col0) = __floats2half2_rn(o2, o3);
            } else {
                float* out = outbase + (size_t)ens * NN * HH;
                if (gr0 < NN)
                    *(float2*)(out + (size_t)gr0 * HH + col0) = make_float2(o0, o1);
                if (gr8 < NN)
                    *(float2*)(out + (size_t)gr8 * HH + col0) = make_float2(o2, o3);
            }
        }
    }
}

// ---------------- pool + head ----------------
__global__ void pool_kernel(const float* __restrict__ hbase,
                            const int* __restrict__ batch) {
    unsigned idx = blockIdx.x * 256u + threadIdx.x;
    unsigned wn = idx >> 5;
    unsigned c = (idx & 31u) << 2;
    if (wn >= 2 * NN) return;
    int ens = wn >= NN;
    unsigned n = wn - (unsigned)ens * NN;
    int g = batch[(size_t)ens * NN + n];
    const float* h = hbase + (size_t)ens * NN * HH;
    float4 v = *(const float4*)(h + (size_t)n * HH + c);
    atomicAdd((float4*)(&g_pool[ens][g * HH + c]), v);
    if (c == 0) atomicAdd(&g_cnt[ens][g], 1.0f);
}

__global__ void head_kernel(const float* __restrict__ W1all,
                            const float* __restrict__ b1all,
                            const float* __restrict__ W2all,
                            const float* __restrict__ b2all,
                            float* __restrict__ out) {
    int g = blockIdx.x;
    int ens = blockIdx.y;
    int c = threadIdx.x;  // 128 threads
    const float* W1 = W1all + (size_t)ens * 16384;
    const float* b1 = b1all + ens * 128;
    const float* W2 = W2all + (size_t)ens * 1280;
    const float* b2 = b2all + ens * 10;
    __shared__ float p[128];
    __shared__ float z[128];
    float cn = fmaxf(g_cnt[ens][g], 1.0f);
    p[c] = g_pool[ens][g * HH + c] / cn;
    __syncthreads();
    float acc = b1[c];
#pragma unroll 4
    for (int k = 0; k < 128; k++) acc += p[k] * W1[k * 128 + c];
    z[c] = fmaxf(acc, 0.f);
    __syncthreads();
    if (c < CC) {
        float y = b2[c];
#pragma unroll 4
        for (int k = 0; k < 128; k++) y += z[k] * W2[k * CC + c];
        out[((size_t)ens * GG + g) * CC + c] = y;
    }
}

// ---------------- driver ----------------
extern "C" void kernel_launch(void* const* d_in, const int* in_sizes, int n_in,
                              void* d_out, int out_size) {
    const float* x     = (const float*)d_in[0];
    const int*   ei    = (const int*)d_in[1];
    const int*   batch = (const int*)d_in[2];
    const float* c1W1  = (const float*)d_in[3];
    const float* c1b1  = (const float*)d_in[4];
    const float* c1W2  = (const float*)d_in[5];
    const float* c1b2  = (const float*)d_in[6];
    const float* c1g   = (const float*)d_in[7];
    const float* c1be  = (const float*)d_in[8];
    const float* c1m   = (const float*)d_in[9];
    const float* c1v   = (const float*)d_in[10];
    const float* c1e   = (const float*)d_in[11];
    const float* csW1  = (const float*)d_in[12];
    const float* csb1  = (const float*)d_in[13];
    const float* csW2  = (const float*)d_in[14];
    const float* csb2  = (const float*)d_in[15];
    const float* csg   = (const float*)d_in[16];
    const float* csbe  = (const float*)d_in[17];
    const float* csm   = (const float*)d_in[18];
    const float* csv   = (const float*)d_in[19];
    const float* cse   = (const float*)d_in[20];
    const float* l1W   = (const float*)d_in[21];
    const float* l1b   = (const float*)d_in[22];
    const float* l2W   = (const float*)d_in[23];
    const float* l2b   = (const float*)d_in[24];
    float* out = (float*)d_out;

    float* hF;
    __half *agg16, *x16, *h16A, *h16B;
    cudaGetSymbolAddress((void**)&agg16, g_agg16);
    cudaGetSymbolAddress((void**)&hF, g_hF);
    cudaGetSymbolAddress((void**)&x16, g_x16);
    cudaGetSymbolAddress((void**)&h16A, g_h16A);
    cudaGetSymbolAddress((void**)&h16B, g_h16B);

    const int SMEM_BYTES = MLP_SMEM_U32 * 4;  // 54,272 B (occ 4)
    cudaFuncSetAttribute(mlp_kernel, cudaFuncAttributeMaxDynamicSharedMemorySize,
                         SMEM_BYTES);

    const int IP_GRID   = 10 + ZB + XB;
    const int E_GRID    = (2 * (EE / 4) + 255) / 256;
    const int AGG_GRID  = (NN * 32 + 255) / 256;      // 2 nodes/warp
    const dim3 MLP_GRID((NN + 63) / 64, 2);
    const int POOL_GRID = (2 * NN * 32 + 255) / 256;

    // 1: init+prep+x16, 2: fill, 3: agg, 4: mlp (profiled slot)
    init_prep_kernel<<<IP_GRID, 256>>>(c1W1, c1W2, csW1, csW2, x);
    fill_kernel<<<E_GRID, 256>>>(ei);

    // layer 0 (conv1, per-ensemble weights: slots 0+ens / 2+ens) -> fp16 out
    agg_kernel<<<AGG_GRID, 256>>>(x16, agg16, c1e, 1);
    mlp_kernel<<<MLP_GRID, 256, SMEM_BYTES>>>(
        agg16, nullptr, h16A, 0, 1, 2, 1, c1b1, c1b2, c1g, c1be, c1m, c1v, 128);

    // layers 1..2 (shared weights: slots 4+l / 7+l) -> fp16 out
    const __half* cur = h16A;
    __half* nxt = h16B;
    for (int l = 0; l < 2; l++) {
        agg_kernel<<<AGG_GRID, 256>>>(cur, agg16, cse + l, 0);
        mlp_kernel<<<MLP_GRID, 256, SMEM_BYTES>>>(
            agg16, nullptr, nxt, 4 + l, 0, 7 + l, 0,
            csb1 + l * 128, csb2 + l * 128,
            csg + l * 128, csbe + l * 128, csm + l * 128, csv + l * 128, 0);
        const __half* tswap = cur;
        cur = nxt;
        nxt = (__half*)tswap;
    }

    // layer 3: fp32 out for pool
    agg_kernel<<<AGG_GRID, 256>>>(cur, agg16, cse + 2, 0);
    mlp_kernel<<<MLP_GRID, 256, SMEM_BYTES>>>(
        agg16, hF, nullptr, 6, 0, 9, 0,
        csb1 + 2 * 128, csb2 + 2 * 128,
        csg + 2 * 128, csbe + 2 * 128, csm + 2 * 128, csv + 2 * 128, 0);

    pool_kernel<<<POOL_GRID, 256>>>(hF, batch);
    head_kernel<<<dim3(GG, 2), 128>>>(l1W, l1b, l2W, l2b, out);
}